// round 1
// baseline (speedup 1.0000x reference)
#include <cuda_runtime.h>
#include <cstdint>

// Problem constants (fixed by the reference setup)
#define S_LEN   2048
#define BATCH   2
#define NHEADS  16
#define DHEAD   128
#define HID     2048
#define H3      6144
#define NROWS   (S_LEN * BATCH)       // 4096 rows for all [s,b,*] matrices
#define INV_NORM 0.08838834764831845f // 1/sqrt(128)

// Scratch in device globals (no cudaMalloc allowed)
__device__ float g_qkv[(size_t)NROWS * H3];   // [4096, 6144]  (s*B+b major)
__device__ float g_ctx[(size_t)NROWS * HID];  // [4096, 2048]

// ---------------------------------------------------------------------------
// SGEMM: C[M,N] = A[M,K] @ B[K,N] (+ bias[N] if bias != nullptr)
// BM=BN=128, BK=16, 256 threads, 8x8 micro-tile.
// ---------------------------------------------------------------------------
#define BMg 128
#define BNg 128
#define BKg 16

__global__ __launch_bounds__(256) void sgemm_kernel(
    const float* __restrict__ A, const float* __restrict__ B,
    const float* __restrict__ bias, float* __restrict__ C,
    int M, int N, int K)
{
    __shared__ float As[BKg][BMg + 4];   // stored transposed: As[k][m]
    __shared__ float Bs[BKg][BNg + 4];

    const int tid = threadIdx.x;
    const int tx  = tid & 15;      // 0..15 -> N micro
    const int ty  = tid >> 4;      // 0..15 -> M micro
    const int m0  = blockIdx.y * BMg;
    const int n0  = blockIdx.x * BNg;

    float acc[8][8];
#pragma unroll
    for (int i = 0; i < 8; ++i)
#pragma unroll
        for (int j = 0; j < 8; ++j) acc[i][j] = 0.f;

    for (int k0 = 0; k0 < K; k0 += BKg) {
        // Load A tile (128 x 16), transpose into As[k][m]
        {
            const int r  = tid >> 2;         // 0..63
            const int cg = (tid & 3) * 4;    // 0,4,8,12
#pragma unroll
            for (int p = 0; p < 2; ++p) {
                const int row = r + p * 64;
                float4 v = *reinterpret_cast<const float4*>(
                    &A[(size_t)(m0 + row) * K + k0 + cg]);
                As[cg + 0][row] = v.x;
                As[cg + 1][row] = v.y;
                As[cg + 2][row] = v.z;
                As[cg + 3][row] = v.w;
            }
        }
        // Load B tile (16 x 128)
        {
            const int r  = tid >> 5;         // 0..7
            const int cg = (tid & 31) * 4;   // 0..124
#pragma unroll
            for (int p = 0; p < 2; ++p) {
                const int row = r + p * 8;
                float4 v = *reinterpret_cast<const float4*>(
                    &B[(size_t)(k0 + row) * N + n0 + cg]);
                *reinterpret_cast<float4*>(&Bs[row][cg]) = v;
            }
        }
        __syncthreads();

#pragma unroll
        for (int k = 0; k < BKg; ++k) {
            float a[8], b[8];
            *reinterpret_cast<float4*>(&a[0]) = *reinterpret_cast<const float4*>(&As[k][ty * 8]);
            *reinterpret_cast<float4*>(&a[4]) = *reinterpret_cast<const float4*>(&As[k][ty * 8 + 4]);
            *reinterpret_cast<float4*>(&b[0]) = *reinterpret_cast<const float4*>(&Bs[k][tx * 8]);
            *reinterpret_cast<float4*>(&b[4]) = *reinterpret_cast<const float4*>(&Bs[k][tx * 8 + 4]);
#pragma unroll
            for (int i = 0; i < 8; ++i)
#pragma unroll
                for (int j = 0; j < 8; ++j)
                    acc[i][j] += a[i] * b[j];
        }
        __syncthreads();
    }

    // Epilogue
#pragma unroll
    for (int i = 0; i < 8; ++i) {
        const size_t row = (size_t)(m0 + ty * 8 + i);
#pragma unroll
        for (int j = 0; j < 8; j += 4) {
            const int col = n0 + tx * 8 + j;
            float4 v;
            v.x = acc[i][j + 0] + (bias ? bias[col + 0] : 0.f);
            v.y = acc[i][j + 1] + (bias ? bias[col + 1] : 0.f);
            v.z = acc[i][j + 2] + (bias ? bias[col + 2] : 0.f);
            v.w = acc[i][j + 3] + (bias ? bias[col + 3] : 0.f);
            *reinterpret_cast<float4*>(&C[row * N + col]) = v;
        }
    }
}

// ---------------------------------------------------------------------------
// Flash-style causal attention, fp32.
// Grid: (S/64, NHEADS, BATCH). 256 threads. Dynamic smem.
// Q tile 64x128 (resident), KV tile 64 (K then V reuse the same buffer),
// online softmax with m/l/cf in smem.
// ---------------------------------------------------------------------------
#define BMA 64
#define BNA 64
#define PADQ 132   // stride for 128-wide tiles
#define PADS 68    // stride for 64-wide score tile

#define SM_Q   0
#define SM_KV  (BMA * PADQ)                 // 8448
#define SM_S   (SM_KV + BMA * PADQ)        // 16896
#define SM_M   (SM_S + BMA * PADS)         // 21248
#define SM_L   (SM_M + BMA)                 // 21312
#define SM_CF  (SM_L + BMA)                 // 21376
#define SM_FLOATS (SM_CF + BMA)             // 21440
#define SM_BYTES  (SM_FLOATS * 4)           // 85760

__global__ __launch_bounds__(256) void attn_kernel(
    const float* __restrict__ qkv,          // [4096, 6144]
    const unsigned char* __restrict__ pmask,// [B,1,S,S] bool
    float* __restrict__ ctx)                // [4096, 2048]
{
    extern __shared__ float sm[];
    float* Qs = sm + SM_Q;
    float* Ks = sm + SM_KV;   // also V
    float* Ss = sm + SM_S;
    float* m_sm  = sm + SM_M;
    float* l_sm  = sm + SM_L;
    float* cf_sm = sm + SM_CF;

    const int tid  = threadIdx.x;
    const int qt   = blockIdx.x;          // q tile
    const int head = blockIdx.y;
    const int bz   = blockIdx.z;
    const int q0   = qt * BMA;

    const int qcol = head * (3 * DHEAD);          // q channel base
    const int kcol = qcol + DHEAD;
    const int vcol = qcol + 2 * DHEAD;

    // Load Q tile: 64 rows x 128 cols
    for (int idx = tid; idx < BMA * 32; idx += 256) {
        const int row = idx >> 5;
        const int c4  = (idx & 31) * 4;
        const size_t grow = (size_t)(q0 + row) * BATCH + bz;
        *reinterpret_cast<float4*>(&Qs[row * PADQ + c4]) =
            *reinterpret_cast<const float4*>(&qkv[grow * H3 + qcol + c4]);
    }
    if (tid < BMA) { m_sm[tid] = -1e30f; l_sm[tid] = 0.f; }
    __syncthreads();

    // phase A thread mapping: 16x16 grid, 4x4 micro
    const int txa = tid & 15;   // kv cols
    const int tya = tid >> 4;   // q rows
    // phase B thread mapping: 16x16 grid, 4 rows x 8 d-cols
    const int txb = tid & 15;
    const int tyb = tid >> 4;

    float oacc[4][8];
#pragma unroll
    for (int i = 0; i < 4; ++i)
#pragma unroll
        for (int j = 0; j < 8; ++j) oacc[i][j] = 0.f;

    const int ntiles = qt + 1;   // causal: kv tiles 0..qt
    for (int jt = 0; jt < ntiles; ++jt) {
        const int j0 = jt * BNA;

        // ---- load K tile ----
        for (int idx = tid; idx < BMA * 32; idx += 256) {
            const int row = idx >> 5;
            const int c4  = (idx & 31) * 4;
            const size_t grow = (size_t)(j0 + row) * BATCH + bz;
            *reinterpret_cast<float4*>(&Ks[row * PADQ + c4]) =
                *reinterpret_cast<const float4*>(&qkv[grow * H3 + kcol + c4]);
        }
        __syncthreads();

        // ---- phase A: S = Q K^T (64x64x128) ----
        {
            float sacc[4][4];
#pragma unroll
            for (int i = 0; i < 4; ++i)
#pragma unroll
                for (int j = 0; j < 4; ++j) sacc[i][j] = 0.f;

            const float* Qb = &Qs[(tya * 4) * PADQ];
            const float* Kb = &Ks[(txa * 4) * PADQ];
#pragma unroll 4
            for (int kk = 0; kk < DHEAD; kk += 4) {
                float4 qa[4], kb[4];
#pragma unroll
                for (int i = 0; i < 4; ++i)
                    qa[i] = *reinterpret_cast<const float4*>(&Qb[i * PADQ + kk]);
#pragma unroll
                for (int j = 0; j < 4; ++j)
                    kb[j] = *reinterpret_cast<const float4*>(&Kb[j * PADQ + kk]);
#pragma unroll
                for (int i = 0; i < 4; ++i)
#pragma unroll
                    for (int j = 0; j < 4; ++j)
                        sacc[i][j] += qa[i].x * kb[j].x + qa[i].y * kb[j].y
                                    + qa[i].z * kb[j].z + qa[i].w * kb[j].w;
            }
            // mask + scale + store scores
#pragma unroll
            for (int i = 0; i < 4; ++i) {
                const int r  = tya * 4 + i;
                const int gq = q0 + r;
                const uchar4 mb = *reinterpret_cast<const uchar4*>(
                    &pmask[((size_t)bz * S_LEN + gq) * S_LEN + j0 + txa * 4]);
                const unsigned char mv[4] = {mb.x, mb.y, mb.z, mb.w};
#pragma unroll
                for (int j = 0; j < 4; ++j) {
                    const int gk = j0 + txa * 4 + j;
                    const bool masked = (gk > gq) || (mv[j] != 0);
                    Ss[r * PADS + txa * 4 + j] =
                        masked ? -10000.0f : sacc[i][j] * INV_NORM;
                }
            }
        }
        __syncthreads();

        // ---- softmax update (rows via tid/4) + load V (overwrites Ks) ----
        {
            const int row = tid >> 2;
            const int sub = tid & 3;
            float* sr = &Ss[row * PADS + sub * 16];
            float mx = -1e30f;
#pragma unroll
            for (int e = 0; e < 16; ++e) mx = fmaxf(mx, sr[e]);
            mx = fmaxf(mx, __shfl_xor_sync(0xffffffffu, mx, 1));
            mx = fmaxf(mx, __shfl_xor_sync(0xffffffffu, mx, 2));
            const float mold = m_sm[row];
            const float mnew = fmaxf(mold, mx);
            const float corr = __expf(mold - mnew);
            float sum = 0.f;
#pragma unroll
            for (int e = 0; e < 16; ++e) {
                const float p = __expf(sr[e] - mnew);
                sr[e] = p;
                sum += p;
            }
            sum += __shfl_xor_sync(0xffffffffu, sum, 1);
            sum += __shfl_xor_sync(0xffffffffu, sum, 2);
            if (sub == 0) {
                m_sm[row]  = mnew;
                l_sm[row]  = l_sm[row] * corr + sum;
                cf_sm[row] = corr;
            }
        }
        for (int idx = tid; idx < BMA * 32; idx += 256) {
            const int row = idx >> 5;
            const int c4  = (idx & 31) * 4;
            const size_t grow = (size_t)(j0 + row) * BATCH + bz;
            *reinterpret_cast<float4*>(&Ks[row * PADQ + c4]) =
                *reinterpret_cast<const float4*>(&qkv[grow * H3 + vcol + c4]);
        }
        __syncthreads();

        // ---- phase B: O = O*cf + P @ V  (64x128x64) ----
        {
            const int rowb = tyb * 4;
            const int colb = txb * 8;
            float fcf[4];
#pragma unroll
            for (int i = 0; i < 4; ++i) fcf[i] = cf_sm[rowb + i];
#pragma unroll
            for (int i = 0; i < 4; ++i)
#pragma unroll
                for (int j = 0; j < 8; ++j) oacc[i][j] *= fcf[i];

#pragma unroll 4
            for (int k = 0; k < BNA; ++k) {
                float p[4];
#pragma unroll
                for (int i = 0; i < 4; ++i) p[i] = Ss[(rowb + i) * PADS + k];
                float4 v0 = *reinterpret_cast<const float4*>(&Ks[k * PADQ + colb]);
                float4 v1 = *reinterpret_cast<const float4*>(&Ks[k * PADQ + colb + 4]);
#pragma unroll
                for (int i = 0; i < 4; ++i) {
                    oacc[i][0] += p[i] * v0.x;
                    oacc[i][1] += p[i] * v0.y;
                    oacc[i][2] += p[i] * v0.z;
                    oacc[i][3] += p[i] * v0.w;
                    oacc[i][4] += p[i] * v1.x;
                    oacc[i][5] += p[i] * v1.y;
                    oacc[i][6] += p[i] * v1.z;
                    oacc[i][7] += p[i] * v1.w;
                }
            }
        }
        __syncthreads();
    }

    // Epilogue: normalize and write context
    {
        const int rowb = tyb * 4;
        const int colb = txb * 8;
#pragma unroll
        for (int i = 0; i < 4; ++i) {
            const float inv_l = 1.0f / l_sm[rowb + i];
            const size_t grow = (size_t)(q0 + rowb + i) * BATCH + bz;
            float4 v0, v1;
            v0.x = oacc[i][0] * inv_l; v0.y = oacc[i][1] * inv_l;
            v0.z = oacc[i][2] * inv_l; v0.w = oacc[i][3] * inv_l;
            v1.x = oacc[i][4] * inv_l; v1.y = oacc[i][5] * inv_l;
            v1.z = oacc[i][6] * inv_l; v1.w = oacc[i][7] * inv_l;
            float* dst = &ctx[grow * HID + head * DHEAD + colb];
            *reinterpret_cast<float4*>(dst)     = v0;
            *reinterpret_cast<float4*>(dst + 4) = v1;
        }
    }
}

// Tail: copy proj_bias after the main output if the harness expects it
__global__ void tail_bias_kernel(const float* __restrict__ bias,
                                 float* __restrict__ out, int n)
{
    const int i = blockIdx.x * blockDim.x + threadIdx.x;
    if (i < n) out[(size_t)NROWS * HID + i] = bias[i];
}

// ---------------------------------------------------------------------------
extern "C" void kernel_launch(void* const* d_in, const int* in_sizes, int n_in,
                              void* d_out, int out_size)
{
    const float*         hidden  = (const float*)d_in[0];
    const unsigned char* amask   = (const unsigned char*)d_in[1];
    const float*         qkv_w   = (const float*)d_in[2];
    const float*         qkv_b   = (const float*)d_in[3];
    const float*         proj_w  = (const float*)d_in[4];
    const float*         proj_b  = (const float*)d_in[5];
    float*               out     = (float*)d_out;

    float* qkv_ptr = nullptr;
    float* ctx_ptr = nullptr;
    cudaGetSymbolAddress((void**)&qkv_ptr, g_qkv);
    cudaGetSymbolAddress((void**)&ctx_ptr, g_ctx);

    cudaFuncSetAttribute(attn_kernel,
                         cudaFuncAttributeMaxDynamicSharedMemorySize, SM_BYTES);

    // 1) QKV GEMM: [4096,2048] @ [2048,6144] + bias
    {
        dim3 grid(H3 / BNg, NROWS / BMg);
        sgemm_kernel<<<grid, 256>>>(hidden, qkv_w, qkv_b, qkv_ptr,
                                    NROWS, H3, HID);
    }
    // 2) Attention
    {
        dim3 grid(S_LEN / BMA, NHEADS, BATCH);
        attn_kernel<<<grid, 256, SM_BYTES>>>(qkv_ptr, amask, ctx_ptr);
    }
    // 3) Output projection: [4096,2048] @ [2048,2048], no bias
    {
        dim3 grid(HID / BNg, NROWS / BMg);
        sgemm_kernel<<<grid, 256>>>(ctx_ptr, proj_w, nullptr, out,
                                    NROWS, HID, HID);
    }
    // 4) Optional bias tail
    const long long main_elems = (long long)NROWS * HID;
    const long long extra = (long long)out_size - main_elems;
    if (extra > 0) {
        const int n = (int)extra;
        tail_bias_kernel<<<(n + 255) / 256, 256>>>(proj_b, out, n);
    }
}

// round 4
// speedup vs baseline: 1.6307x; 1.6307x over previous
#include <cuda_runtime.h>
#include <cuda_bf16.h>
#include <cstdint>

// Problem constants (fixed by the reference setup)
#define S_LEN   2048
#define BATCH   2
#define NHEADS  16
#define DHEAD   128
#define HID     2048
#define H3      6144
#define NROWS   (S_LEN * BATCH)       // 4096
#define INV_NORM 0.08838834764831845f // 1/sqrt(128)

// ---------------- device-global scratch (no cudaMalloc allowed) ----------------
__device__ float g_qkv[(size_t)NROWS * H3];   // [4096, 6144] fp32
__device__ float g_ctx[(size_t)NROWS * HID];  // [4096, 2048] fp32
__device__ __nv_bfloat16 g_Ah[(size_t)NROWS * HID];
__device__ __nv_bfloat16 g_Al[(size_t)NROWS * HID];
__device__ __nv_bfloat16 g_Wqh[(size_t)H3 * HID];   // qkv_w transposed: [6144, 2048]
__device__ __nv_bfloat16 g_Wql[(size_t)H3 * HID];
__device__ __nv_bfloat16 g_Wph[(size_t)HID * HID];  // proj_w transposed: [2048, 2048]
__device__ __nv_bfloat16 g_Wpl[(size_t)HID * HID];
__device__ __nv_bfloat16 g_Ch[(size_t)NROWS * HID];
__device__ __nv_bfloat16 g_Cl[(size_t)NROWS * HID];

// ---------------- helpers (all non-'a' ISA: sm_80-level PTX only) ----------------
__device__ __forceinline__ uint32_t smem_u32(const void* p) {
    uint32_t a;
    asm("{ .reg .u64 t; cvta.to.shared.u64 t, %1; cvt.u32.u64 %0, t; }" : "=r"(a) : "l"(p));
    return a;
}
#define SWZ(o) ((o) ^ (((o) >> 3) & 0x70))

__device__ __forceinline__ void cp16(uint32_t dst, const void* src) {
    asm volatile("cp.async.cg.shared.global [%0], [%1], 16;\n" :: "r"(dst), "l"(src));
}
__device__ __forceinline__ void ldm_x4(uint32_t addr, uint32_t& r0, uint32_t& r1,
                                       uint32_t& r2, uint32_t& r3) {
    asm volatile("ldmatrix.sync.aligned.m8n8.x4.shared.b16 {%0,%1,%2,%3}, [%4];"
                 : "=r"(r0), "=r"(r1), "=r"(r2), "=r"(r3) : "r"(addr));
}
__device__ __forceinline__ void mma16816(float* c, const uint32_t* a, const uint32_t* b) {
    asm volatile(
        "mma.sync.aligned.m16n8k16.row.col.f32.bf16.bf16.f32 "
        "{%0,%1,%2,%3}, {%4,%5,%6,%7}, {%8,%9}, {%0,%1,%2,%3};"
        : "+f"(c[0]), "+f"(c[1]), "+f"(c[2]), "+f"(c[3])
        : "r"(a[0]), "r"(a[1]), "r"(a[2]), "r"(a[3]), "r"(b[0]), "r"(b[1]));
}

// ---------------------------------------------------------------------------
// Conversion kernels
// ---------------------------------------------------------------------------
__global__ __launch_bounds__(256) void split_kernel(
    const float* __restrict__ x, __nv_bfloat16* __restrict__ hi,
    __nv_bfloat16* __restrict__ lo, int n4)  // n4 = n/4
{
    const int i = blockIdx.x * blockDim.x + threadIdx.x;
    if (i < n4) {
        float4 v = reinterpret_cast<const float4*>(x)[i];
        float f[4] = {v.x, v.y, v.z, v.w};
        __nv_bfloat16 h[4], l[4];
#pragma unroll
        for (int j = 0; j < 4; ++j) {
            h[j] = __float2bfloat16(f[j]);
            l[j] = __float2bfloat16(f[j] - __bfloat162float(h[j]));
        }
        reinterpret_cast<__nv_bfloat162*>(hi)[i * 2 + 0] = __nv_bfloat162(h[0], h[1]);
        reinterpret_cast<__nv_bfloat162*>(hi)[i * 2 + 1] = __nv_bfloat162(h[2], h[3]);
        reinterpret_cast<__nv_bfloat162*>(lo)[i * 2 + 0] = __nv_bfloat162(l[0], l[1]);
        reinterpret_cast<__nv_bfloat162*>(lo)[i * 2 + 1] = __nv_bfloat162(l[2], l[3]);
    }
}

// Transpose + split: W [K,N] fp32 -> Th/Tl [N,K] bf16
__global__ void tsplit_kernel(const float* __restrict__ W,
                              __nv_bfloat16* __restrict__ Th,
                              __nv_bfloat16* __restrict__ Tl, int K, int N)
{
    __shared__ float t[32][33];
    const int x = blockIdx.x * 32 + threadIdx.x;  // N index (read)
    const int y0 = blockIdx.y * 32;               // K base
#pragma unroll
    for (int j = threadIdx.y; j < 32; j += 8)
        t[j][threadIdx.x] = W[(size_t)(y0 + j) * N + x];
    __syncthreads();
    const int kx = y0 + threadIdx.x;              // K index (write)
#pragma unroll
    for (int j = threadIdx.y; j < 32; j += 8) {
        const float v = t[threadIdx.x][j];
        const __nv_bfloat16 h = __float2bfloat16(v);
        const __nv_bfloat16 l = __float2bfloat16(v - __bfloat162float(h));
        const size_t o = (size_t)(blockIdx.x * 32 + j) * K + kx;
        Th[o] = h;
        Tl[o] = l;
    }
}

// ---------------------------------------------------------------------------
// mma.sync split-bf16 GEMM: C[M,N] = A[M,K] @ Bt[N,K]^T (+bias)
// 128x128 tile, BK=64, 8 warps (2m x 4n), 3-stage cp.async pipeline.
// Products accumulated: Ah*Bh + Ah*Bl + Al*Bh (fp32 accum).
// ---------------------------------------------------------------------------
#define TILE_B  16384                 // 128 rows x 128 bytes (64 bf16)
#define STAGE_B (4 * TILE_B)          // Ah, Al, Bh, Bl
#define GSM_BYTES (3 * STAGE_B)       // 196608

__device__ __forceinline__ void load_tile(uint32_t sbase, const __nv_bfloat16* g,
                                          int row0, int k0, int K)
{
    const int tid = threadIdx.x;
#pragma unroll
    for (int i = 0; i < 4; ++i) {
        const int u = tid + i * 256;          // 1024 16B units
        const int r = u >> 3, cu = u & 7;
        const uint32_t dst = sbase + SWZ(r * 128 + cu * 16);
        const char* src = (const char*)g + ((size_t)(row0 + r) * K + k0) * 2 + cu * 16;
        cp16(dst, src);
    }
}

__global__ __launch_bounds__(256) void gemm_mma(
    const __nv_bfloat16* __restrict__ Ah, const __nv_bfloat16* __restrict__ Al,
    const __nv_bfloat16* __restrict__ Bh, const __nv_bfloat16* __restrict__ Bl,
    const float* __restrict__ bias, float* __restrict__ C, int M, int N, int K)
{
    extern __shared__ char smem[];
    const uint32_t sb = smem_u32(smem);
    const int tid  = threadIdx.x;
    const int warp = tid >> 5, lane = tid & 31;
    const int wm = warp >> 2, wn = warp & 3;     // 2 x 4 warp grid
    const int n0 = blockIdx.x * 128, m0 = blockIdx.y * 128;

    float acc[4][4][4];
#pragma unroll
    for (int mi = 0; mi < 4; ++mi)
#pragma unroll
        for (int ni = 0; ni < 4; ++ni)
#pragma unroll
            for (int e = 0; e < 4; ++e) acc[mi][ni][e] = 0.f;

    const int NC = K / 64;
    // prologue: fill 3 stages
#pragma unroll
    for (int s = 0; s < 3; ++s) {
        if (s < NC) {
            const uint32_t bb = sb + s * STAGE_B;
            load_tile(bb,              Ah, m0, s * 64, K);
            load_tile(bb + TILE_B,     Al, m0, s * 64, K);
            load_tile(bb + 2 * TILE_B, Bh, n0, s * 64, K);
            load_tile(bb + 3 * TILE_B, Bl, n0, s * 64, K);
        }
        asm volatile("cp.async.commit_group;\n" ::: "memory");
    }

    // ldmatrix lane-address components
    const int a_r  = (lane & 7) + ((lane >> 3) & 1) * 8;  // row within m16
    const int a_kb = lane >> 4;                           // k-halfblock 0/1
    const int b_r  = (lane & 7) + (lane >> 4) * 8;        // row within n16
    const int b_kb = (lane >> 3) & 1;

    for (int c = 0; c < NC; ++c) {
        asm volatile("cp.async.wait_group 2;\n" ::: "memory");
        __syncthreads();
        const uint32_t bb   = sb + (c % 3) * STAGE_B;
        const uint32_t aihB = bb;
        const uint32_t ailB = bb + TILE_B;
        const uint32_t bihB = bb + 2 * TILE_B;
        const uint32_t bilB = bb + 3 * TILE_B;

#pragma unroll
        for (int kk = 0; kk < 4; ++kk) {
            const int kby = kk * 32;
            uint32_t ah[4][4], al[4][4], bh[4][2], bl[4][2];
#pragma unroll
            for (int mi = 0; mi < 4; ++mi) {
                const int row = wm * 64 + mi * 16 + a_r;
                const uint32_t off = SWZ(row * 128 + kby + a_kb * 16);
                ldm_x4(aihB + off, ah[mi][0], ah[mi][1], ah[mi][2], ah[mi][3]);
                ldm_x4(ailB + off, al[mi][0], al[mi][1], al[mi][2], al[mi][3]);
            }
#pragma unroll
            for (int p = 0; p < 2; ++p) {
                const int row = wn * 32 + p * 16 + b_r;
                const uint32_t off = SWZ(row * 128 + kby + b_kb * 16);
                ldm_x4(bihB + off, bh[2 * p][0], bh[2 * p][1], bh[2 * p + 1][0], bh[2 * p + 1][1]);
                ldm_x4(bilB + off, bl[2 * p][0], bl[2 * p][1], bl[2 * p + 1][0], bl[2 * p + 1][1]);
            }
#pragma unroll
            for (int mi = 0; mi < 4; ++mi)
#pragma unroll
                for (int ni = 0; ni < 4; ++ni) {
                    mma16816(acc[mi][ni], ah[mi], bh[ni]);
                    mma16816(acc[mi][ni], ah[mi], bl[ni]);
                    mma16816(acc[mi][ni], al[mi], bh[ni]);
                }
        }
        __syncthreads();
        if (c + 3 < NC) {
            const int k0 = (c + 3) * 64;
            load_tile(bb,              Ah, m0, k0, K);
            load_tile(bb + TILE_B,     Al, m0, k0, K);
            load_tile(bb + 2 * TILE_B, Bh, n0, k0, K);
            load_tile(bb + 3 * TILE_B, Bl, n0, k0, K);
        }
        asm volatile("cp.async.commit_group;\n" ::: "memory");
    }

    // epilogue
    const int r0 = lane >> 2;
    const int c0 = (lane & 3) * 2;
#pragma unroll
    for (int mi = 0; mi < 4; ++mi) {
#pragma unroll
        for (int ni = 0; ni < 4; ++ni) {
            const int col  = n0 + wn * 32 + ni * 8 + c0;
            const int row1 = m0 + wm * 64 + mi * 16 + r0;
            float2 b2 = bias ? *reinterpret_cast<const float2*>(&bias[col])
                             : make_float2(0.f, 0.f);
            float2 v0 = make_float2(acc[mi][ni][0] + b2.x, acc[mi][ni][1] + b2.y);
            float2 v1 = make_float2(acc[mi][ni][2] + b2.x, acc[mi][ni][3] + b2.y);
            *reinterpret_cast<float2*>(&C[(size_t)row1 * N + col]) = v0;
            *reinterpret_cast<float2*>(&C[(size_t)(row1 + 8) * N + col]) = v1;
        }
    }
}

// ---------------------------------------------------------------------------
// Flash-style causal attention, fp32 (unchanged from passing round-1 kernel)
// ---------------------------------------------------------------------------
#define BMA 64
#define BNA 64
#define PADQ 132
#define PADS 68

#define SM_Q   0
#define SM_KV  (BMA * PADQ)
#define SM_S   (SM_KV + BMA * PADQ)
#define SM_M   (SM_S + BMA * PADS)
#define SM_L   (SM_M + BMA)
#define SM_CF  (SM_L + BMA)
#define SM_FLOATS (SM_CF + BMA)
#define SM_BYTES  (SM_FLOATS * 4)

__global__ __launch_bounds__(256) void attn_kernel(
    const float* __restrict__ qkv,
    const unsigned char* __restrict__ pmask,
    float* __restrict__ ctx)
{
    extern __shared__ float sm[];
    float* Qs = sm + SM_Q;
    float* Ks = sm + SM_KV;
    float* Ss = sm + SM_S;
    float* m_sm  = sm + SM_M;
    float* l_sm  = sm + SM_L;
    float* cf_sm = sm + SM_CF;

    const int tid  = threadIdx.x;
    const int qt   = blockIdx.x;
    const int head = blockIdx.y;
    const int bz   = blockIdx.z;
    const int q0   = qt * BMA;

    const int qcol = head * (3 * DHEAD);
    const int kcol = qcol + DHEAD;
    const int vcol = qcol + 2 * DHEAD;

    for (int idx = tid; idx < BMA * 32; idx += 256) {
        const int row = idx >> 5;
        const int c4  = (idx & 31) * 4;
        const size_t grow = (size_t)(q0 + row) * BATCH + bz;
        *reinterpret_cast<float4*>(&Qs[row * PADQ + c4]) =
            *reinterpret_cast<const float4*>(&qkv[grow * H3 + qcol + c4]);
    }
    if (tid < BMA) { m_sm[tid] = -1e30f; l_sm[tid] = 0.f; }
    __syncthreads();

    const int txa = tid & 15;
    const int tya = tid >> 4;
    const int txb = tid & 15;
    const int tyb = tid >> 4;

    float oacc[4][8];
#pragma unroll
    for (int i = 0; i < 4; ++i)
#pragma unroll
        for (int j = 0; j < 8; ++j) oacc[i][j] = 0.f;

    const int ntiles = qt + 1;
    for (int jt = 0; jt < ntiles; ++jt) {
        const int j0 = jt * BNA;

        for (int idx = tid; idx < BMA * 32; idx += 256) {
            const int row = idx >> 5;
            const int c4  = (idx & 31) * 4;
            const size_t grow = (size_t)(j0 + row) * BATCH + bz;
            *reinterpret_cast<float4*>(&Ks[row * PADQ + c4]) =
                *reinterpret_cast<const float4*>(&qkv[grow * H3 + kcol + c4]);
        }
        __syncthreads();

        {
            float sacc[4][4];
#pragma unroll
            for (int i = 0; i < 4; ++i)
#pragma unroll
                for (int j = 0; j < 4; ++j) sacc[i][j] = 0.f;

            const float* Qb = &Qs[(tya * 4) * PADQ];
            const float* Kb = &Ks[(txa * 4) * PADQ];
#pragma unroll 4
            for (int kk = 0; kk < DHEAD; kk += 4) {
                float4 qa[4], kb[4];
#pragma unroll
                for (int i = 0; i < 4; ++i)
                    qa[i] = *reinterpret_cast<const float4*>(&Qb[i * PADQ + kk]);
#pragma unroll
                for (int j = 0; j < 4; ++j)
                    kb[j] = *reinterpret_cast<const float4*>(&Kb[j * PADQ + kk]);
#pragma unroll
                for (int i = 0; i < 4; ++i)
#pragma unroll
                    for (int j = 0; j < 4; ++j)
                        sacc[i][j] += qa[i].x * kb[j].x + qa[i].y * kb[j].y
                                    + qa[i].z * kb[j].z + qa[i].w * kb[j].w;
            }
#pragma unroll
            for (int i = 0; i < 4; ++i) {
                const int r  = tya * 4 + i;
                const int gq = q0 + r;
                const uchar4 mb = *reinterpret_cast<const uchar4*>(
                    &pmask[((size_t)bz * S_LEN + gq) * S_LEN + j0 + txa * 4]);
                const unsigned char mv[4] = {mb.x, mb.y, mb.z, mb.w};
#pragma unroll
                for (int j = 0; j < 4; ++j) {
                    const int gk = j0 + txa * 4 + j;
                    const bool masked = (gk > gq) || (mv[j] != 0);
                    Ss[r * PADS + txa * 4 + j] =
                        masked ? -10000.0f : sacc[i][j] * INV_NORM;
                }
            }
        }
        __syncthreads();

        {
            const int row = tid >> 2;
            const int sub = tid & 3;
            float* sr = &Ss[row * PADS + sub * 16];
            float mx = -1e30f;
#pragma unroll
            for (int e = 0; e < 16; ++e) mx = fmaxf(mx, sr[e]);
            mx = fmaxf(mx, __shfl_xor_sync(0xffffffffu, mx, 1));
            mx = fmaxf(mx, __shfl_xor_sync(0xffffffffu, mx, 2));
            const float mold = m_sm[row];
            const float mnew = fmaxf(mold, mx);
            const float corr = __expf(mold - mnew);
            float sum = 0.f;
#pragma unroll
            for (int e = 0; e < 16; ++e) {
                const float p = __expf(sr[e] - mnew);
                sr[e] = p;
                sum += p;
            }
            sum += __shfl_xor_sync(0xffffffffu, sum, 1);
            sum += __shfl_xor_sync(0xffffffffu, sum, 2);
            if (sub == 0) {
                m_sm[row]  = mnew;
                l_sm[row]  = l_sm[row] * corr + sum;
                cf_sm[row] = corr;
            }
        }
        for (int idx = tid; idx < BMA * 32; idx += 256) {
            const int row = idx >> 5;
            const int c4  = (idx & 31) * 4;
            const size_t grow = (size_t)(j0 + row) * BATCH + bz;
            *reinterpret_cast<float4*>(&Ks[row * PADQ + c4]) =
                *reinterpret_cast<const float4*>(&qkv[grow * H3 + vcol + c4]);
        }
        __syncthreads();

        {
            const int rowb = tyb * 4;
            const int colb = txb * 8;
            float fcf[4];
#pragma unroll
            for (int i = 0; i < 4; ++i) fcf[i] = cf_sm[rowb + i];
#pragma unroll
            for (int i = 0; i < 4; ++i)
#pragma unroll
                for (int j = 0; j < 8; ++j) oacc[i][j] *= fcf[i];

#pragma unroll 4
            for (int k = 0; k < BNA; ++k) {
                float p[4];
#pragma unroll
                for (int i = 0; i < 4; ++i) p[i] = Ss[(rowb + i) * PADS + k];
                float4 v0 = *reinterpret_cast<const float4*>(&Ks[k * PADQ + colb]);
                float4 v1 = *reinterpret_cast<const float4*>(&Ks[k * PADQ + colb + 4]);
#pragma unroll
                for (int i = 0; i < 4; ++i) {
                    oacc[i][0] += p[i] * v0.x;
                    oacc[i][1] += p[i] * v0.y;
                    oacc[i][2] += p[i] * v0.z;
                    oacc[i][3] += p[i] * v0.w;
                    oacc[i][4] += p[i] * v1.x;
                    oacc[i][5] += p[i] * v1.y;
                    oacc[i][6] += p[i] * v1.z;
                    oacc[i][7] += p[i] * v1.w;
                }
            }
        }
        __syncthreads();
    }

    {
        const int rowb = tyb * 4;
        const int colb = txb * 8;
#pragma unroll
        for (int i = 0; i < 4; ++i) {
            const float inv_l = 1.0f / l_sm[rowb + i];
            const size_t grow = (size_t)(q0 + rowb + i) * BATCH + bz;
            float4 v0, v1;
            v0.x = oacc[i][0] * inv_l; v0.y = oacc[i][1] * inv_l;
            v0.z = oacc[i][2] * inv_l; v0.w = oacc[i][3] * inv_l;
            v1.x = oacc[i][4] * inv_l; v1.y = oacc[i][5] * inv_l;
            v1.z = oacc[i][6] * inv_l; v1.w = oacc[i][7] * inv_l;
            float* dst = &ctx[grow * HID + head * DHEAD + colb];
            *reinterpret_cast<float4*>(dst)     = v0;
            *reinterpret_cast<float4*>(dst + 4) = v1;
        }
    }
}

// Tail: copy proj_bias after the main output if the harness expects it
__global__ void tail_bias_kernel(const float* __restrict__ bias,
                                 float* __restrict__ out, int n)
{
    const int i = blockIdx.x * blockDim.x + threadIdx.x;
    if (i < n) out[(size_t)NROWS * HID + i] = bias[i];
}

// ---------------------------------------------------------------------------
extern "C" void kernel_launch(void* const* d_in, const int* in_sizes, int n_in,
                              void* d_out, int out_size)
{
    const float*         hidden  = (const float*)d_in[0];
    const unsigned char* amask   = (const unsigned char*)d_in[1];
    const float*         qkv_w   = (const float*)d_in[2];
    const float*         qkv_b   = (const float*)d_in[3];
    const float*         proj_w  = (const float*)d_in[4];
    const float*         proj_b  = (const float*)d_in[5];
    float*               out     = (float*)d_out;

    float *qkv_ptr, *ctx_ptr;
    __nv_bfloat16 *Ah, *Al, *Wqh, *Wql, *Wph, *Wpl, *Ch, *Cl;
    cudaGetSymbolAddress((void**)&qkv_ptr, g_qkv);
    cudaGetSymbolAddress((void**)&ctx_ptr, g_ctx);
    cudaGetSymbolAddress((void**)&Ah,  g_Ah);
    cudaGetSymbolAddress((void**)&Al,  g_Al);
    cudaGetSymbolAddress((void**)&Wqh, g_Wqh);
    cudaGetSymbolAddress((void**)&Wql, g_Wql);
    cudaGetSymbolAddress((void**)&Wph, g_Wph);
    cudaGetSymbolAddress((void**)&Wpl, g_Wpl);
    cudaGetSymbolAddress((void**)&Ch,  g_Ch);
    cudaGetSymbolAddress((void**)&Cl,  g_Cl);

    cudaFuncSetAttribute(attn_kernel,
                         cudaFuncAttributeMaxDynamicSharedMemorySize, SM_BYTES);
    cudaFuncSetAttribute(gemm_mma,
                         cudaFuncAttributeMaxDynamicSharedMemorySize, GSM_BYTES);

    // 0) conversions
    {
        const int n4 = (NROWS * HID) / 4;
        split_kernel<<<(n4 + 255) / 256, 256>>>(hidden, Ah, Al, n4);
        dim3 tb(32, 8);
        tsplit_kernel<<<dim3(H3 / 32, HID / 32), tb>>>(qkv_w, Wqh, Wql, HID, H3);
        tsplit_kernel<<<dim3(HID / 32, HID / 32), tb>>>(proj_w, Wph, Wpl, HID, HID);
    }
    // 1) QKV GEMM (mma.sync): [4096,2048] @ [2048,6144] + bias
    {
        dim3 grid(H3 / 128, NROWS / 128);
        gemm_mma<<<grid, 256, GSM_BYTES>>>(Ah, Al, Wqh, Wql, qkv_b, qkv_ptr,
                                           NROWS, H3, HID);
    }
    // 2) Attention (fp32 flash)
    {
        dim3 grid(S_LEN / BMA, NHEADS, BATCH);
        attn_kernel<<<grid, 256, SM_BYTES>>>(qkv_ptr, amask, ctx_ptr);
    }
    // 3) split context, then proj GEMM (mma.sync)
    {
        const int n4 = (NROWS * HID) / 4;
        split_kernel<<<(n4 + 255) / 256, 256>>>(ctx_ptr, Ch, Cl, n4);
        dim3 grid(HID / 128, NROWS / 128);
        gemm_mma<<<grid, 256, GSM_BYTES>>>(Ch, Cl, Wph, Wpl, nullptr, out,
                                           NROWS, HID, HID);
    }
    // 4) Optional bias tail
    const long long main_elems = (long long)NROWS * HID;
    const long long extra = (long long)out_size - main_elems;
    if (extra > 0) {
        const int n = (int)extra;
        tail_bias_kernel<<<(n + 255) / 256, 256>>>(proj_b, out, n);
    }
}

// round 5
// speedup vs baseline: 2.1576x; 1.3231x over previous
#include <cuda_runtime.h>
#include <cuda_bf16.h>
#include <cstdint>

// Problem constants (fixed by the reference setup)
#define S_LEN   2048
#define BATCH   2
#define NHEADS  16
#define DHEAD   128
#define HID     2048
#define H3      6144
#define NROWS   (S_LEN * BATCH)       // 4096
#define INV_NORM 0.08838834764831845f // 1/sqrt(128)

// ---------------- device-global scratch (no cudaMalloc allowed) ----------------
__device__ float g_qkv[(size_t)NROWS * H3];            // [4096, 6144] fp32
__device__ __nv_bfloat16 g_Ah[(size_t)NROWS * HID];
__device__ __nv_bfloat16 g_Al[(size_t)NROWS * HID];
__device__ __nv_bfloat16 g_Wqh[(size_t)H3 * HID];      // qkv_w^T [6144,2048]
__device__ __nv_bfloat16 g_Wql[(size_t)H3 * HID];
__device__ __nv_bfloat16 g_Wph[(size_t)HID * HID];     // proj_w^T [2048,2048]
__device__ __nv_bfloat16 g_Wpl[(size_t)HID * HID];
__device__ __nv_bfloat16 g_Ch[(size_t)NROWS * HID];    // attention out hi
__device__ __nv_bfloat16 g_Cl[(size_t)NROWS * HID];    // attention out lo
__device__ __nv_bfloat16 g_qkvh[(size_t)NROWS * H3];   // qkv split hi
__device__ __nv_bfloat16 g_qkvl[(size_t)NROWS * H3];   // qkv split lo
__device__ __nv_bfloat16 g_Vth[(size_t)BATCH * NHEADS * DHEAD * S_LEN]; // V^T [b][h][d][s]
__device__ __nv_bfloat16 g_Vtl[(size_t)BATCH * NHEADS * DHEAD * S_LEN];

// ---------------- helpers (sm_80-level PTX only; no 'a'-gated instructions) ----
__device__ __forceinline__ uint32_t smem_u32(const void* p) {
    uint32_t a;
    asm("{ .reg .u64 t; cvta.to.shared.u64 t, %1; cvt.u32.u64 %0, t; }" : "=r"(a) : "l"(p));
    return a;
}
#define SWZ(o) ((o) ^ (((o) >> 3) & 0x70))

__device__ __forceinline__ void cp16(uint32_t dst, const void* src) {
    asm volatile("cp.async.cg.shared.global [%0], [%1], 16;\n" :: "r"(dst), "l"(src));
}
__device__ __forceinline__ void ldm_x4(uint32_t addr, uint32_t& r0, uint32_t& r1,
                                       uint32_t& r2, uint32_t& r3) {
    asm volatile("ldmatrix.sync.aligned.m8n8.x4.shared.b16 {%0,%1,%2,%3}, [%4];"
                 : "=r"(r0), "=r"(r1), "=r"(r2), "=r"(r3) : "r"(addr));
}
__device__ __forceinline__ void mma16816(float* c, const uint32_t* a, const uint32_t* b) {
    asm volatile(
        "mma.sync.aligned.m16n8k16.row.col.f32.bf16.bf16.f32 "
        "{%0,%1,%2,%3}, {%4,%5,%6,%7}, {%8,%9}, {%0,%1,%2,%3};"
        : "+f"(c[0]), "+f"(c[1]), "+f"(c[2]), "+f"(c[3])
        : "r"(a[0]), "r"(a[1]), "r"(a[2]), "r"(a[3]), "r"(b[0]), "r"(b[1]));
}
__device__ __forceinline__ uint32_t pack_hi(float x, float y) {
    __nv_bfloat162 t(__float2bfloat16(x), __float2bfloat16(y));
    return *reinterpret_cast<uint32_t*>(&t);
}
__device__ __forceinline__ uint32_t pack_lo(float x, float y,
                                            __nv_bfloat16 hx, __nv_bfloat16 hy) {
    __nv_bfloat162 t(__float2bfloat16(x - __bfloat162float(hx)),
                     __float2bfloat16(y - __bfloat162float(hy)));
    return *reinterpret_cast<uint32_t*>(&t);
}

// ---------------------------------------------------------------------------
// Conversion kernels
// ---------------------------------------------------------------------------
__global__ __launch_bounds__(256) void split_kernel(
    const float* __restrict__ x, __nv_bfloat16* __restrict__ hi,
    __nv_bfloat16* __restrict__ lo, int n4)
{
    const int i = blockIdx.x * blockDim.x + threadIdx.x;
    if (i < n4) {
        float4 v = reinterpret_cast<const float4*>(x)[i];
        float f[4] = {v.x, v.y, v.z, v.w};
        __nv_bfloat16 h[4], l[4];
#pragma unroll
        for (int j = 0; j < 4; ++j) {
            h[j] = __float2bfloat16(f[j]);
            l[j] = __float2bfloat16(f[j] - __bfloat162float(h[j]));
        }
        reinterpret_cast<__nv_bfloat162*>(hi)[i * 2 + 0] = __nv_bfloat162(h[0], h[1]);
        reinterpret_cast<__nv_bfloat162*>(hi)[i * 2 + 1] = __nv_bfloat162(h[2], h[3]);
        reinterpret_cast<__nv_bfloat162*>(lo)[i * 2 + 0] = __nv_bfloat162(l[0], l[1]);
        reinterpret_cast<__nv_bfloat162*>(lo)[i * 2 + 1] = __nv_bfloat162(l[2], l[3]);
    }
}

// Transpose + split: W [K,N] fp32 -> Th/Tl [N,K] bf16
__global__ void tsplit_kernel(const float* __restrict__ W,
                              __nv_bfloat16* __restrict__ Th,
                              __nv_bfloat16* __restrict__ Tl, int K, int N)
{
    __shared__ float t[32][33];
    const int x = blockIdx.x * 32 + threadIdx.x;
    const int y0 = blockIdx.y * 32;
#pragma unroll
    for (int j = threadIdx.y; j < 32; j += 8)
        t[j][threadIdx.x] = W[(size_t)(y0 + j) * N + x];
    __syncthreads();
    const int kx = y0 + threadIdx.x;
#pragma unroll
    for (int j = threadIdx.y; j < 32; j += 8) {
        const float v = t[threadIdx.x][j];
        const __nv_bfloat16 h = __float2bfloat16(v);
        const __nv_bfloat16 l = __float2bfloat16(v - __bfloat162float(h));
        const size_t o = (size_t)(blockIdx.x * 32 + j) * K + kx;
        Th[o] = h;
        Tl[o] = l;
    }
}

// V transpose + split: g_qkv v-region -> Vt [b][h][d][s] bf16 hi/lo
__global__ void vtrans_kernel(const float* __restrict__ qkv,
                              __nv_bfloat16* __restrict__ Vth,
                              __nv_bfloat16* __restrict__ Vtl)
{
    __shared__ float t[32][33];
    const int s0 = blockIdx.x * 32, d0 = blockIdx.y * 32;
    const int bh = blockIdx.z;
    const int b = bh >> 4, h = bh & 15;
    const int col = h * 384 + 256 + d0 + threadIdx.x;
#pragma unroll
    for (int j = threadIdx.y; j < 32; j += 8) {
        const size_t grow = (size_t)(s0 + j) * 2 + b;
        t[j][threadIdx.x] = qkv[grow * H3 + col];
    }
    __syncthreads();
#pragma unroll
    for (int j = threadIdx.y; j < 32; j += 8) {
        const float v = t[threadIdx.x][j];   // element (s=s0+tx, d=d0+j)
        const size_t o = ((size_t)bh * DHEAD + d0 + j) * S_LEN + s0 + threadIdx.x;
        const __nv_bfloat16 hh = __float2bfloat16(v);
        Vth[o] = hh;
        Vtl[o] = __float2bfloat16(v - __bfloat162float(hh));
    }
}

// ---------------------------------------------------------------------------
// mma.sync split-bf16 GEMM (unchanged, validated): C = A @ Bt^T (+bias)
// ---------------------------------------------------------------------------
#define TILE_B  16384
#define STAGE_B (4 * TILE_B)
#define GSM_BYTES (3 * STAGE_B)

__device__ __forceinline__ void load_tile(uint32_t sbase, const __nv_bfloat16* g,
                                          int row0, int k0, int K)
{
    const int tid = threadIdx.x;
#pragma unroll
    for (int i = 0; i < 4; ++i) {
        const int u = tid + i * 256;
        const int r = u >> 3, cu = u & 7;
        const uint32_t dst = sbase + SWZ(r * 128 + cu * 16);
        const char* src = (const char*)g + ((size_t)(row0 + r) * K + k0) * 2 + cu * 16;
        cp16(dst, src);
    }
}

__global__ __launch_bounds__(256) void gemm_mma(
    const __nv_bfloat16* __restrict__ Ah, const __nv_bfloat16* __restrict__ Al,
    const __nv_bfloat16* __restrict__ Bh, const __nv_bfloat16* __restrict__ Bl,
    const float* __restrict__ bias, float* __restrict__ C, int M, int N, int K)
{
    extern __shared__ char smem[];
    const uint32_t sb = smem_u32(smem);
    const int tid  = threadIdx.x;
    const int warp = tid >> 5, lane = tid & 31;
    const int wm = warp >> 2, wn = warp & 3;
    const int n0 = blockIdx.x * 128, m0 = blockIdx.y * 128;

    float acc[4][4][4];
#pragma unroll
    for (int mi = 0; mi < 4; ++mi)
#pragma unroll
        for (int ni = 0; ni < 4; ++ni)
#pragma unroll
            for (int e = 0; e < 4; ++e) acc[mi][ni][e] = 0.f;

    const int NC = K / 64;
#pragma unroll
    for (int s = 0; s < 3; ++s) {
        if (s < NC) {
            const uint32_t bb = sb + s * STAGE_B;
            load_tile(bb,              Ah, m0, s * 64, K);
            load_tile(bb + TILE_B,     Al, m0, s * 64, K);
            load_tile(bb + 2 * TILE_B, Bh, n0, s * 64, K);
            load_tile(bb + 3 * TILE_B, Bl, n0, s * 64, K);
        }
        asm volatile("cp.async.commit_group;\n" ::: "memory");
    }

    const int a_r  = (lane & 7) + ((lane >> 3) & 1) * 8;
    const int a_kb = lane >> 4;
    const int b_r  = (lane & 7) + (lane >> 4) * 8;
    const int b_kb = (lane >> 3) & 1;

    for (int c = 0; c < NC; ++c) {
        asm volatile("cp.async.wait_group 2;\n" ::: "memory");
        __syncthreads();
        const uint32_t bb   = sb + (c % 3) * STAGE_B;
        const uint32_t aihB = bb;
        const uint32_t ailB = bb + TILE_B;
        const uint32_t bihB = bb + 2 * TILE_B;
        const uint32_t bilB = bb + 3 * TILE_B;

#pragma unroll
        for (int kk = 0; kk < 4; ++kk) {
            const int kby = kk * 32;
            uint32_t ah[4][4], al[4][4], bh[4][2], bl[4][2];
#pragma unroll
            for (int mi = 0; mi < 4; ++mi) {
                const int row = wm * 64 + mi * 16 + a_r;
                const uint32_t off = SWZ(row * 128 + kby + a_kb * 16);
                ldm_x4(aihB + off, ah[mi][0], ah[mi][1], ah[mi][2], ah[mi][3]);
                ldm_x4(ailB + off, al[mi][0], al[mi][1], al[mi][2], al[mi][3]);
            }
#pragma unroll
            for (int p = 0; p < 2; ++p) {
                const int row = wn * 32 + p * 16 + b_r;
                const uint32_t off = SWZ(row * 128 + kby + b_kb * 16);
                ldm_x4(bihB + off, bh[2 * p][0], bh[2 * p][1], bh[2 * p + 1][0], bh[2 * p + 1][1]);
                ldm_x4(bilB + off, bl[2 * p][0], bl[2 * p][1], bl[2 * p + 1][0], bl[2 * p + 1][1]);
            }
#pragma unroll
            for (int mi = 0; mi < 4; ++mi)
#pragma unroll
                for (int ni = 0; ni < 4; ++ni) {
                    mma16816(acc[mi][ni], ah[mi], bh[ni]);
                    mma16816(acc[mi][ni], ah[mi], bl[ni]);
                    mma16816(acc[mi][ni], al[mi], bh[ni]);
                }
        }
        __syncthreads();
        if (c + 3 < NC) {
            const int k0 = (c + 3) * 64;
            load_tile(bb,              Ah, m0, k0, K);
            load_tile(bb + TILE_B,     Al, m0, k0, K);
            load_tile(bb + 2 * TILE_B, Bh, n0, k0, K);
            load_tile(bb + 3 * TILE_B, Bl, n0, k0, K);
        }
        asm volatile("cp.async.commit_group;\n" ::: "memory");
    }

    const int r0 = lane >> 2;
    const int c0 = (lane & 3) * 2;
#pragma unroll
    for (int mi = 0; mi < 4; ++mi) {
#pragma unroll
        for (int ni = 0; ni < 4; ++ni) {
            const int col  = n0 + wn * 32 + ni * 8 + c0;
            const int row1 = m0 + wm * 64 + mi * 16 + r0;
            float2 b2 = bias ? *reinterpret_cast<const float2*>(&bias[col])
                             : make_float2(0.f, 0.f);
            float2 v0 = make_float2(acc[mi][ni][0] + b2.x, acc[mi][ni][1] + b2.y);
            float2 v1 = make_float2(acc[mi][ni][2] + b2.x, acc[mi][ni][3] + b2.y);
            *reinterpret_cast<float2*>(&C[(size_t)row1 * N + col]) = v0;
            *reinterpret_cast<float2*>(&C[(size_t)(row1 + 8) * N + col]) = v1;
        }
    }
}

// ---------------------------------------------------------------------------
// Tensor-core flash attention (split-bf16 mma for S=QK^T and O=PV).
// BM=128 q rows/CTA, BN=64 kv tile, 8 warps (4m x 2n for S; 4m x 2n for O).
// Writes Ch/Cl (bf16 split of context) directly.
// ---------------------------------------------------------------------------
#define AT_QH   0
#define AT_QL   32768
#define AT_KH   65536
#define AT_KL   81920
#define AT_VH   98304
#define AT_VL   114688
#define AT_PH   131072
#define AT_PL   147456
#define AT_WMAX 163840
#define AT_WSUM (AT_WMAX + 1024)
#define AT_M    (AT_WSUM + 1024)
#define AT_L    (AT_M + 512)
#define AT_CF   (AT_L + 512)
#define ATT_SMEM (AT_CF + 512)   // 167424 bytes

__global__ __launch_bounds__(256) void attn_mma(
    const __nv_bfloat16* __restrict__ QKh, const __nv_bfloat16* __restrict__ QKl,
    const __nv_bfloat16* __restrict__ Vth, const __nv_bfloat16* __restrict__ Vtl,
    const unsigned char* __restrict__ pmask,
    __nv_bfloat16* __restrict__ Ch, __nv_bfloat16* __restrict__ Cl)
{
    extern __shared__ char smem[];
    const uint32_t sb = smem_u32(smem);
    float* warpmax = reinterpret_cast<float*>(smem + AT_WMAX);
    float* warpsum = reinterpret_cast<float*>(smem + AT_WSUM);
    float* m_sm    = reinterpret_cast<float*>(smem + AT_M);
    float* l_sm    = reinterpret_cast<float*>(smem + AT_L);
    float* cf_sm   = reinterpret_cast<float*>(smem + AT_CF);

    const int tid = threadIdx.x, warp = tid >> 5, lane = tid & 31;
    const int wm = warp >> 1, wn = warp & 1;
    const int qt = blockIdx.x, head = blockIdx.y, bz = blockIdx.z;
    const int q0 = qt * 128;
    const int qcol = head * 384, kcol = qcol + 128;
    const int bh = bz * NHEADS + head;

    // ---- load Q tile (128 x 128, hi+lo, two 64-col subtiles each) ----
#pragma unroll
    for (int t = 0; t < 2; ++t) {
#pragma unroll
        for (int i = 0; i < 4; ++i) {
            const int u = tid + i * 256;
            const int r = u >> 3, cu = u & 7;
            const size_t grow = (size_t)(q0 + r) * 2 + bz;
            const size_t eoff = (grow * H3 + qcol + t * 64 + cu * 8) * 2;
            const uint32_t off = SWZ(r * 128 + cu * 16);
            cp16(sb + AT_QH + t * 16384 + off, (const char*)QKh + eoff);
            cp16(sb + AT_QL + t * 16384 + off, (const char*)QKl + eoff);
        }
    }
    if (tid < 128) { m_sm[tid] = -1e30f; l_sm[tid] = 0.f; }
    asm volatile("cp.async.commit_group;\n" ::: "memory");

    const int a_r  = (lane & 7) + ((lane >> 3) & 1) * 8;
    const int a_kb = lane >> 4;
    const int b_r  = (lane & 7) + (lane >> 4) * 8;
    const int b_kb = (lane >> 3) & 1;
    const int r0   = lane >> 2;
    const int c0   = (lane & 3) * 2;

    float oacc[2][8][4];
#pragma unroll
    for (int mi = 0; mi < 2; ++mi)
#pragma unroll
        for (int ni = 0; ni < 8; ++ni)
#pragma unroll
            for (int e = 0; e < 4; ++e) oacc[mi][ni][e] = 0.f;

    const int ntiles = 2 * qt + 2;
    for (int jt = 0; jt < ntiles; ++jt) {
        const int j0 = jt * 64;

        // ---- load K (64x128 hi/lo) and Vt (128x64 hi/lo) ----
#pragma unroll
        for (int t = 0; t < 2; ++t) {
#pragma unroll
            for (int i = 0; i < 2; ++i) {
                const int u = tid + i * 256;
                const int r = u >> 3, cu = u & 7;
                const size_t grow = (size_t)(j0 + r) * 2 + bz;
                const size_t eoff = (grow * H3 + kcol + t * 64 + cu * 8) * 2;
                const uint32_t off = SWZ(r * 128 + cu * 16);
                cp16(sb + AT_KH + t * 8192 + off, (const char*)QKh + eoff);
                cp16(sb + AT_KL + t * 8192 + off, (const char*)QKl + eoff);
            }
        }
#pragma unroll
        for (int i = 0; i < 4; ++i) {
            const int u = tid + i * 256;
            const int r = u >> 3, cu = u & 7;
            const size_t eoff = (((size_t)bh * DHEAD + r) * S_LEN + j0 + cu * 8) * 2;
            const uint32_t off = SWZ(r * 128 + cu * 16);
            cp16(sb + AT_VH + off, (const char*)Vth + eoff);
            cp16(sb + AT_VL + off, (const char*)Vtl + eoff);
        }
        asm volatile("cp.async.commit_group;\n" ::: "memory");
        asm volatile("cp.async.wait_group 0;\n" ::: "memory");
        __syncthreads();   // A: tiles ready

        // ---- S-phase: S = Q K^T (128x64x128, split-bf16) ----
        float sacc[2][4][4];
#pragma unroll
        for (int mi = 0; mi < 2; ++mi)
#pragma unroll
            for (int ni = 0; ni < 4; ++ni)
#pragma unroll
                for (int e = 0; e < 4; ++e) sacc[mi][ni][e] = 0.f;

#pragma unroll
        for (int kk = 0; kk < 8; ++kk) {
            const int t = kk >> 2, kby = (kk & 3) * 32;
            uint32_t qh[2][4], ql[2][4], kh[4][2], kl[4][2];
#pragma unroll
            for (int mi = 0; mi < 2; ++mi) {
                const int row = wm * 32 + mi * 16 + a_r;
                const uint32_t off = SWZ(row * 128 + kby + a_kb * 16);
                ldm_x4(sb + AT_QH + t * 16384 + off, qh[mi][0], qh[mi][1], qh[mi][2], qh[mi][3]);
                ldm_x4(sb + AT_QL + t * 16384 + off, ql[mi][0], ql[mi][1], ql[mi][2], ql[mi][3]);
            }
#pragma unroll
            for (int p = 0; p < 2; ++p) {
                const int row = wn * 32 + p * 16 + b_r;
                const uint32_t off = SWZ(row * 128 + kby + b_kb * 16);
                ldm_x4(sb + AT_KH + t * 8192 + off,
                       kh[2 * p][0], kh[2 * p][1], kh[2 * p + 1][0], kh[2 * p + 1][1]);
                ldm_x4(sb + AT_KL + t * 8192 + off,
                       kl[2 * p][0], kl[2 * p][1], kl[2 * p + 1][0], kl[2 * p + 1][1]);
            }
#pragma unroll
            for (int mi = 0; mi < 2; ++mi)
#pragma unroll
                for (int ni = 0; ni < 4; ++ni) {
                    mma16816(sacc[mi][ni], qh[mi], kh[ni]);
                    mma16816(sacc[mi][ni], qh[mi], kl[ni]);
                    mma16816(sacc[mi][ni], ql[mi], kh[ni]);
                }
        }

        // ---- scale + mask + per-warp row max ----
#pragma unroll
        for (int mi = 0; mi < 2; ++mi) {
            const int lr = wm * 32 + mi * 16 + r0;
            const int gr0 = q0 + lr, gr1 = gr0 + 8;
            float rm0 = -1e30f, rm1 = -1e30f;
#pragma unroll
            for (int ni = 0; ni < 4; ++ni) {
                const int gc = j0 + wn * 32 + ni * 8 + c0;
                const uchar2 mA = *reinterpret_cast<const uchar2*>(
                    &pmask[((size_t)bz * S_LEN + gr0) * S_LEN + gc]);
                const uchar2 mB = *reinterpret_cast<const uchar2*>(
                    &pmask[((size_t)bz * S_LEN + gr1) * S_LEN + gc]);
                float* s = sacc[mi][ni];
                s[0] = (gc     > gr0 || mA.x) ? -10000.f : s[0] * INV_NORM;
                s[1] = (gc + 1 > gr0 || mA.y) ? -10000.f : s[1] * INV_NORM;
                s[2] = (gc     > gr1 || mB.x) ? -10000.f : s[2] * INV_NORM;
                s[3] = (gc + 1 > gr1 || mB.y) ? -10000.f : s[3] * INV_NORM;
                rm0 = fmaxf(rm0, fmaxf(s[0], s[1]));
                rm1 = fmaxf(rm1, fmaxf(s[2], s[3]));
            }
            rm0 = fmaxf(rm0, __shfl_xor_sync(0xffffffffu, rm0, 1));
            rm0 = fmaxf(rm0, __shfl_xor_sync(0xffffffffu, rm0, 2));
            rm1 = fmaxf(rm1, __shfl_xor_sync(0xffffffffu, rm1, 1));
            rm1 = fmaxf(rm1, __shfl_xor_sync(0xffffffffu, rm1, 2));
            if ((lane & 3) == 0) {
                warpmax[wn * 128 + lr]     = rm0;
                warpmax[wn * 128 + lr + 8] = rm1;
            }
        }
        __syncthreads();   // B
        if (tid < 128) {
            const float mold = m_sm[tid];
            const float mnew = fmaxf(mold, fmaxf(warpmax[tid], warpmax[128 + tid]));
            m_sm[tid]  = mnew;
            cf_sm[tid] = __expf(mold - mnew);
        }
        __syncthreads();   // C

        // ---- exp + store P (hi/lo) + row sums ----
#pragma unroll
        for (int mi = 0; mi < 2; ++mi) {
            const int lr = wm * 32 + mi * 16 + r0;
            const float m0v = m_sm[lr], m1v = m_sm[lr + 8];
            float rs0 = 0.f, rs1 = 0.f;
#pragma unroll
            for (int ni = 0; ni < 4; ++ni) {
                float* s = sacc[mi][ni];
                const float p0 = __expf(s[0] - m0v);
                const float p1 = __expf(s[1] - m0v);
                const float p2 = __expf(s[2] - m1v);
                const float p3 = __expf(s[3] - m1v);
                rs0 += p0 + p1;
                rs1 += p2 + p3;
                const int cbyte = (wn * 32 + ni * 8 + c0) * 2;
                const __nv_bfloat16 h0 = __float2bfloat16(p0);
                const __nv_bfloat16 h1 = __float2bfloat16(p1);
                const __nv_bfloat16 h2 = __float2bfloat16(p2);
                const __nv_bfloat16 h3 = __float2bfloat16(p3);
                *reinterpret_cast<uint32_t*>(smem + AT_PH + SWZ(lr * 128 + cbyte)) =
                    pack_hi(p0, p1);
                *reinterpret_cast<uint32_t*>(smem + AT_PH + SWZ((lr + 8) * 128 + cbyte)) =
                    pack_hi(p2, p3);
                *reinterpret_cast<uint32_t*>(smem + AT_PL + SWZ(lr * 128 + cbyte)) =
                    pack_lo(p0, p1, h0, h1);
                *reinterpret_cast<uint32_t*>(smem + AT_PL + SWZ((lr + 8) * 128 + cbyte)) =
                    pack_lo(p2, p3, h2, h3);
            }
            rs0 += __shfl_xor_sync(0xffffffffu, rs0, 1);
            rs0 += __shfl_xor_sync(0xffffffffu, rs0, 2);
            rs1 += __shfl_xor_sync(0xffffffffu, rs1, 1);
            rs1 += __shfl_xor_sync(0xffffffffu, rs1, 2);
            if ((lane & 3) == 0) {
                warpsum[wn * 128 + lr]     = rs0;
                warpsum[wn * 128 + lr + 8] = rs1;
            }
        }
        __syncthreads();   // D
        if (tid < 128)
            l_sm[tid] = l_sm[tid] * cf_sm[tid] + warpsum[tid] + warpsum[128 + tid];

        // ---- O-phase: O = O*cf + P @ Vt (128x128x64, split-bf16) ----
#pragma unroll
        for (int mi = 0; mi < 2; ++mi) {
            const int lr = wm * 32 + mi * 16 + r0;
            const float cfa = cf_sm[lr], cfb = cf_sm[lr + 8];
#pragma unroll
            for (int ni = 0; ni < 8; ++ni) {
                oacc[mi][ni][0] *= cfa; oacc[mi][ni][1] *= cfa;
                oacc[mi][ni][2] *= cfb; oacc[mi][ni][3] *= cfb;
            }
        }
#pragma unroll
        for (int kk = 0; kk < 4; ++kk) {
            const int kby = kk * 32;
            uint32_t ph[2][4], pl[2][4], vh[8][2], vl[8][2];
#pragma unroll
            for (int mi = 0; mi < 2; ++mi) {
                const int row = wm * 32 + mi * 16 + a_r;
                const uint32_t off = SWZ(row * 128 + kby + a_kb * 16);
                ldm_x4(sb + AT_PH + off, ph[mi][0], ph[mi][1], ph[mi][2], ph[mi][3]);
                ldm_x4(sb + AT_PL + off, pl[mi][0], pl[mi][1], pl[mi][2], pl[mi][3]);
            }
#pragma unroll
            for (int p = 0; p < 4; ++p) {
                const int row = wn * 64 + p * 16 + b_r;
                const uint32_t off = SWZ(row * 128 + kby + b_kb * 16);
                ldm_x4(sb + AT_VH + off,
                       vh[2 * p][0], vh[2 * p][1], vh[2 * p + 1][0], vh[2 * p + 1][1]);
                ldm_x4(sb + AT_VL + off,
                       vl[2 * p][0], vl[2 * p][1], vl[2 * p + 1][0], vl[2 * p + 1][1]);
            }
#pragma unroll
            for (int mi = 0; mi < 2; ++mi)
#pragma unroll
                for (int ni = 0; ni < 8; ++ni) {
                    mma16816(oacc[mi][ni], ph[mi], vh[ni]);
                    mma16816(oacc[mi][ni], ph[mi], vl[ni]);
                    mma16816(oacc[mi][ni], pl[mi], vh[ni]);
                }
        }
        __syncthreads();   // E: protect K/V/P smem reuse
    }

    // ---- epilogue: normalize, split to bf16 hi/lo, write Ch/Cl ----
#pragma unroll
    for (int mi = 0; mi < 2; ++mi) {
        const int lr = wm * 32 + mi * 16 + r0;
        const float il0 = 1.0f / l_sm[lr];
        const float il1 = 1.0f / l_sm[lr + 8];
        const size_t grow0 = (size_t)(q0 + lr) * 2 + bz;
        const size_t grow1 = grow0 + 16;
#pragma unroll
        for (int ni = 0; ni < 8; ++ni) {
            const int col = head * DHEAD + wn * 64 + ni * 8 + c0;
            const float o0 = oacc[mi][ni][0] * il0, o1 = oacc[mi][ni][1] * il0;
            const float o2 = oacc[mi][ni][2] * il1, o3 = oacc[mi][ni][3] * il1;
            const __nv_bfloat16 h0 = __float2bfloat16(o0), h1 = __float2bfloat16(o1);
            const __nv_bfloat16 h2 = __float2bfloat16(o2), h3 = __float2bfloat16(o3);
            *reinterpret_cast<uint32_t*>(&Ch[grow0 * HID + col]) = pack_hi(o0, o1);
            *reinterpret_cast<uint32_t*>(&Ch[grow1 * HID + col]) = pack_hi(o2, o3);
            *reinterpret_cast<uint32_t*>(&Cl[grow0 * HID + col]) = pack_lo(o0, o1, h0, h1);
            *reinterpret_cast<uint32_t*>(&Cl[grow1 * HID + col]) = pack_lo(o2, o3, h2, h3);
        }
    }
}

// Tail: copy proj_bias after the main output if the harness expects it
__global__ void tail_bias_kernel(const float* __restrict__ bias,
                                 float* __restrict__ out, int n)
{
    const int i = blockIdx.x * blockDim.x + threadIdx.x;
    if (i < n) out[(size_t)NROWS * HID + i] = bias[i];
}

// ---------------------------------------------------------------------------
extern "C" void kernel_launch(void* const* d_in, const int* in_sizes, int n_in,
                              void* d_out, int out_size)
{
    const float*         hidden  = (const float*)d_in[0];
    const unsigned char* amask   = (const unsigned char*)d_in[1];
    const float*         qkv_w   = (const float*)d_in[2];
    const float*         qkv_b   = (const float*)d_in[3];
    const float*         proj_w  = (const float*)d_in[4];
    const float*         proj_b  = (const float*)d_in[5];
    float*               out     = (float*)d_out;

    float* qkv_ptr;
    __nv_bfloat16 *Ah, *Al, *Wqh, *Wql, *Wph, *Wpl, *Ch, *Cl, *QKh, *QKl, *Vth, *Vtl;
    cudaGetSymbolAddress((void**)&qkv_ptr, g_qkv);
    cudaGetSymbolAddress((void**)&Ah,   g_Ah);
    cudaGetSymbolAddress((void**)&Al,   g_Al);
    cudaGetSymbolAddress((void**)&Wqh,  g_Wqh);
    cudaGetSymbolAddress((void**)&Wql,  g_Wql);
    cudaGetSymbolAddress((void**)&Wph,  g_Wph);
    cudaGetSymbolAddress((void**)&Wpl,  g_Wpl);
    cudaGetSymbolAddress((void**)&Ch,   g_Ch);
    cudaGetSymbolAddress((void**)&Cl,   g_Cl);
    cudaGetSymbolAddress((void**)&QKh,  g_qkvh);
    cudaGetSymbolAddress((void**)&QKl,  g_qkvl);
    cudaGetSymbolAddress((void**)&Vth,  g_Vth);
    cudaGetSymbolAddress((void**)&Vtl,  g_Vtl);

    cudaFuncSetAttribute(gemm_mma,
                         cudaFuncAttributeMaxDynamicSharedMemorySize, GSM_BYTES);
    cudaFuncSetAttribute(attn_mma,
                         cudaFuncAttributeMaxDynamicSharedMemorySize, ATT_SMEM);

    // 0) input conversions
    {
        const int n4 = (NROWS * HID) / 4;
        split_kernel<<<(n4 + 255) / 256, 256>>>(hidden, Ah, Al, n4);
        dim3 tb(32, 8);
        tsplit_kernel<<<dim3(H3 / 32, HID / 32), tb>>>(qkv_w, Wqh, Wql, HID, H3);
        tsplit_kernel<<<dim3(HID / 32, HID / 32), tb>>>(proj_w, Wph, Wpl, HID, HID);
    }
    // 1) QKV GEMM (mma.sync): [4096,2048] @ [2048,6144] + bias -> fp32
    {
        dim3 grid(H3 / 128, NROWS / 128);
        gemm_mma<<<grid, 256, GSM_BYTES>>>(Ah, Al, Wqh, Wql, qkv_b, qkv_ptr,
                                           NROWS, H3, HID);
    }
    // 2) qkv split (q,k consumed; v region unused) + V transpose-split
    {
        const int n4 = (NROWS * H3) / 4;
        split_kernel<<<(n4 + 255) / 256, 256>>>(qkv_ptr, QKh, QKl, n4);
        dim3 tb(32, 8);
        vtrans_kernel<<<dim3(S_LEN / 32, DHEAD / 32, BATCH * NHEADS), tb>>>(
            qkv_ptr, Vth, Vtl);
    }
    // 3) Attention (tensor cores) -> Ch/Cl
    {
        dim3 grid(S_LEN / 128, NHEADS, BATCH);
        attn_mma<<<grid, 256, ATT_SMEM>>>(QKh, QKl, Vth, Vtl, amask, Ch, Cl);
    }
    // 4) Output projection (mma.sync): [4096,2048] @ [2048,2048]
    {
        dim3 grid(HID / 128, NROWS / 128);
        gemm_mma<<<grid, 256, GSM_BYTES>>>(Ch, Cl, Wph, Wpl, nullptr, out,
                                           NROWS, HID, HID);
    }
    // 5) Optional bias tail
    const long long main_elems = (long long)NROWS * HID;
    const long long extra = (long long)out_size - main_elems;
    if (extra > 0) {
        const int n = (int)extra;
        tail_bias_kernel<<<(n + 255) / 256, 256>>>(proj_b, out, n);
    }
}

// round 6
// speedup vs baseline: 3.3821x; 1.5675x over previous
#include <cuda_runtime.h>
#include <cuda_bf16.h>
#include <cstdint>

// Problem constants (fixed by the reference setup)
#define S_LEN   2048
#define BATCH   2
#define NHEADS  16
#define DHEAD   128
#define HID     2048
#define H3      6144
#define NROWS   (S_LEN * BATCH)       // 4096
#define INV_NORM 0.08838834764831845f // 1/sqrt(128)

// ---------------- device-global scratch (no cudaMalloc allowed) ----------------
__device__ __nv_bfloat16 g_Ah[(size_t)NROWS * HID];
__device__ __nv_bfloat16 g_Al[(size_t)NROWS * HID];
__device__ __nv_bfloat16 g_Wqh[(size_t)H3 * HID];      // qkv_w^T [6144,2048]
__device__ __nv_bfloat16 g_Wql[(size_t)H3 * HID];
__device__ __nv_bfloat16 g_Wph[(size_t)HID * HID];     // proj_w^T [2048,2048]
__device__ __nv_bfloat16 g_Wpl[(size_t)HID * HID];
__device__ __nv_bfloat16 g_Ch[(size_t)NROWS * HID];    // attention out hi
__device__ __nv_bfloat16 g_Cl[(size_t)NROWS * HID];    // attention out lo
__device__ __nv_bfloat16 g_qkvh[(size_t)NROWS * H3];   // qkv split hi (gemm writes)
__device__ __nv_bfloat16 g_qkvl[(size_t)NROWS * H3];   // qkv split lo
__device__ __nv_bfloat16 g_Vth[(size_t)BATCH * NHEADS * DHEAD * S_LEN]; // V^T [b][h][d][s]
__device__ __nv_bfloat16 g_Vtl[(size_t)BATCH * NHEADS * DHEAD * S_LEN];

// ---------------- helpers (sm_80-level PTX only) ----------------
__device__ __forceinline__ uint32_t smem_u32(const void* p) {
    uint32_t a;
    asm("{ .reg .u64 t; cvta.to.shared.u64 t, %1; cvt.u32.u64 %0, t; }" : "=r"(a) : "l"(p));
    return a;
}
#define SWZ(o) ((o) ^ (((o) >> 3) & 0x70))

__device__ __forceinline__ void cp16(uint32_t dst, const void* src) {
    asm volatile("cp.async.cg.shared.global [%0], [%1], 16;\n" :: "r"(dst), "l"(src));
}
__device__ __forceinline__ void ldm_x4(uint32_t addr, uint32_t& r0, uint32_t& r1,
                                       uint32_t& r2, uint32_t& r3) {
    asm volatile("ldmatrix.sync.aligned.m8n8.x4.shared.b16 {%0,%1,%2,%3}, [%4];"
                 : "=r"(r0), "=r"(r1), "=r"(r2), "=r"(r3) : "r"(addr));
}
__device__ __forceinline__ void mma16816(float* c, const uint32_t* a, const uint32_t* b) {
    asm volatile(
        "mma.sync.aligned.m16n8k16.row.col.f32.bf16.bf16.f32 "
        "{%0,%1,%2,%3}, {%4,%5,%6,%7}, {%8,%9}, {%0,%1,%2,%3};"
        : "+f"(c[0]), "+f"(c[1]), "+f"(c[2]), "+f"(c[3])
        : "r"(a[0]), "r"(a[1]), "r"(a[2]), "r"(a[3]), "r"(b[0]), "r"(b[1]));
}
__device__ __forceinline__ uint32_t pack_hi(float x, float y) {
    __nv_bfloat162 t(__float2bfloat16(x), __float2bfloat16(y));
    return *reinterpret_cast<uint32_t*>(&t);
}
__device__ __forceinline__ uint32_t pack_lo(float x, float y,
                                            __nv_bfloat16 hx, __nv_bfloat16 hy) {
    __nv_bfloat162 t(__float2bfloat16(x - __bfloat162float(hx)),
                     __float2bfloat16(y - __bfloat162float(hy)));
    return *reinterpret_cast<uint32_t*>(&t);
}

// ---------------------------------------------------------------------------
// Conversion kernels
// ---------------------------------------------------------------------------
__global__ __launch_bounds__(256) void split_kernel(
    const float* __restrict__ x, __nv_bfloat16* __restrict__ hi,
    __nv_bfloat16* __restrict__ lo, int n4)
{
    const int i = blockIdx.x * blockDim.x + threadIdx.x;
    if (i < n4) {
        float4 v = reinterpret_cast<const float4*>(x)[i];
        float f[4] = {v.x, v.y, v.z, v.w};
        __nv_bfloat16 h[4], l[4];
#pragma unroll
        for (int j = 0; j < 4; ++j) {
            h[j] = __float2bfloat16(f[j]);
            l[j] = __float2bfloat16(f[j] - __bfloat162float(h[j]));
        }
        reinterpret_cast<__nv_bfloat162*>(hi)[i * 2 + 0] = __nv_bfloat162(h[0], h[1]);
        reinterpret_cast<__nv_bfloat162*>(hi)[i * 2 + 1] = __nv_bfloat162(h[2], h[3]);
        reinterpret_cast<__nv_bfloat162*>(lo)[i * 2 + 0] = __nv_bfloat162(l[0], l[1]);
        reinterpret_cast<__nv_bfloat162*>(lo)[i * 2 + 1] = __nv_bfloat162(l[2], l[3]);
    }
}

// Transpose + split: W [K,N] fp32 -> Th/Tl [N,K] bf16
__global__ void tsplit_kernel(const float* __restrict__ W,
                              __nv_bfloat16* __restrict__ Th,
                              __nv_bfloat16* __restrict__ Tl, int K, int N)
{
    __shared__ float t[32][33];
    const int x = blockIdx.x * 32 + threadIdx.x;
    const int y0 = blockIdx.y * 32;
#pragma unroll
    for (int j = threadIdx.y; j < 32; j += 8)
        t[j][threadIdx.x] = W[(size_t)(y0 + j) * N + x];
    __syncthreads();
    const int kx = y0 + threadIdx.x;
#pragma unroll
    for (int j = threadIdx.y; j < 32; j += 8) {
        const float v = t[threadIdx.x][j];
        const __nv_bfloat16 h = __float2bfloat16(v);
        const __nv_bfloat16 l = __float2bfloat16(v - __bfloat162float(h));
        const size_t o = (size_t)(blockIdx.x * 32 + j) * K + kx;
        Th[o] = h;
        Tl[o] = l;
    }
}

// V transpose (bf16 hi/lo pass-through): qkv split v-region -> Vt [b][h][d][s]
__global__ void vtrans_kernel(const __nv_bfloat16* __restrict__ qh,
                              const __nv_bfloat16* __restrict__ ql,
                              __nv_bfloat16* __restrict__ Vth,
                              __nv_bfloat16* __restrict__ Vtl)
{
    __shared__ __nv_bfloat16 th[32][33], tl[32][33];
    const int s0 = blockIdx.x * 32, d0 = blockIdx.y * 32;
    const int bh = blockIdx.z;
    const int b = bh >> 4, h = bh & 15;
    const int col = h * 384 + 256 + d0 + threadIdx.x;
#pragma unroll
    for (int j = threadIdx.y; j < 32; j += 8) {
        const size_t grow = (size_t)(s0 + j) * 2 + b;
        th[j][threadIdx.x] = qh[grow * H3 + col];
        tl[j][threadIdx.x] = ql[grow * H3 + col];
    }
    __syncthreads();
#pragma unroll
    for (int j = threadIdx.y; j < 32; j += 8) {
        const size_t o = ((size_t)bh * DHEAD + d0 + j) * S_LEN + s0 + threadIdx.x;
        Vth[o] = th[threadIdx.x][j];
        Vtl[o] = tl[threadIdx.x][j];
    }
}

// ---------------------------------------------------------------------------
// mma.sync split-bf16 GEMM: C = A @ Bt^T (+bias).
// Optional split epilogue: if Chi != nullptr, write bf16 hi/lo instead of fp32.
// ---------------------------------------------------------------------------
#define TILE_B  16384
#define STAGE_B (4 * TILE_B)
#define GSM_BYTES (3 * STAGE_B)

__device__ __forceinline__ void load_tile(uint32_t sbase, const __nv_bfloat16* g,
                                          int row0, int k0, int K)
{
    const int tid = threadIdx.x;
#pragma unroll
    for (int i = 0; i < 4; ++i) {
        const int u = tid + i * 256;
        const int r = u >> 3, cu = u & 7;
        const uint32_t dst = sbase + SWZ(r * 128 + cu * 16);
        const char* src = (const char*)g + ((size_t)(row0 + r) * K + k0) * 2 + cu * 16;
        cp16(dst, src);
    }
}

__global__ __launch_bounds__(256) void gemm_mma(
    const __nv_bfloat16* __restrict__ Ah, const __nv_bfloat16* __restrict__ Al,
    const __nv_bfloat16* __restrict__ Bh, const __nv_bfloat16* __restrict__ Bl,
    const float* __restrict__ bias, float* __restrict__ C,
    __nv_bfloat16* __restrict__ Chi, __nv_bfloat16* __restrict__ Clo,
    int M, int N, int K)
{
    extern __shared__ char smem[];
    const uint32_t sb = smem_u32(smem);
    const int tid  = threadIdx.x;
    const int warp = tid >> 5, lane = tid & 31;
    const int wm = warp >> 2, wn = warp & 3;
    const int n0 = blockIdx.x * 128, m0 = blockIdx.y * 128;

    float acc[4][4][4];
#pragma unroll
    for (int mi = 0; mi < 4; ++mi)
#pragma unroll
        for (int ni = 0; ni < 4; ++ni)
#pragma unroll
            for (int e = 0; e < 4; ++e) acc[mi][ni][e] = 0.f;

    const int NC = K / 64;
#pragma unroll
    for (int s = 0; s < 3; ++s) {
        if (s < NC) {
            const uint32_t bb = sb + s * STAGE_B;
            load_tile(bb,              Ah, m0, s * 64, K);
            load_tile(bb + TILE_B,     Al, m0, s * 64, K);
            load_tile(bb + 2 * TILE_B, Bh, n0, s * 64, K);
            load_tile(bb + 3 * TILE_B, Bl, n0, s * 64, K);
        }
        asm volatile("cp.async.commit_group;\n" ::: "memory");
    }

    const int a_r  = (lane & 7) + ((lane >> 3) & 1) * 8;
    const int a_kb = lane >> 4;
    const int b_r  = (lane & 7) + (lane >> 4) * 8;
    const int b_kb = (lane >> 3) & 1;

    for (int c = 0; c < NC; ++c) {
        asm volatile("cp.async.wait_group 2;\n" ::: "memory");
        __syncthreads();
        const uint32_t bb   = sb + (c % 3) * STAGE_B;
        const uint32_t aihB = bb;
        const uint32_t ailB = bb + TILE_B;
        const uint32_t bihB = bb + 2 * TILE_B;
        const uint32_t bilB = bb + 3 * TILE_B;

#pragma unroll
        for (int kk = 0; kk < 4; ++kk) {
            const int kby = kk * 32;
            uint32_t ah[4][4], al[4][4], bh[4][2], bl[4][2];
#pragma unroll
            for (int mi = 0; mi < 4; ++mi) {
                const int row = wm * 64 + mi * 16 + a_r;
                const uint32_t off = SWZ(row * 128 + kby + a_kb * 16);
                ldm_x4(aihB + off, ah[mi][0], ah[mi][1], ah[mi][2], ah[mi][3]);
                ldm_x4(ailB + off, al[mi][0], al[mi][1], al[mi][2], al[mi][3]);
            }
#pragma unroll
            for (int p = 0; p < 2; ++p) {
                const int row = wn * 32 + p * 16 + b_r;
                const uint32_t off = SWZ(row * 128 + kby + b_kb * 16);
                ldm_x4(bihB + off, bh[2 * p][0], bh[2 * p][1], bh[2 * p + 1][0], bh[2 * p + 1][1]);
                ldm_x4(bilB + off, bl[2 * p][0], bl[2 * p][1], bl[2 * p + 1][0], bl[2 * p + 1][1]);
            }
#pragma unroll
            for (int mi = 0; mi < 4; ++mi)
#pragma unroll
                for (int ni = 0; ni < 4; ++ni) {
                    mma16816(acc[mi][ni], ah[mi], bh[ni]);
                    mma16816(acc[mi][ni], ah[mi], bl[ni]);
                    mma16816(acc[mi][ni], al[mi], bh[ni]);
                }
        }
        __syncthreads();
        if (c + 3 < NC) {
            const int k0 = (c + 3) * 64;
            load_tile(bb,              Ah, m0, k0, K);
            load_tile(bb + TILE_B,     Al, m0, k0, K);
            load_tile(bb + 2 * TILE_B, Bh, n0, k0, K);
            load_tile(bb + 3 * TILE_B, Bl, n0, k0, K);
        }
        asm volatile("cp.async.commit_group;\n" ::: "memory");
    }

    const int r0 = lane >> 2;
    const int c0 = (lane & 3) * 2;
#pragma unroll
    for (int mi = 0; mi < 4; ++mi) {
#pragma unroll
        for (int ni = 0; ni < 4; ++ni) {
            const int col  = n0 + wn * 32 + ni * 8 + c0;
            const int row1 = m0 + wm * 64 + mi * 16 + r0;
            float2 b2 = bias ? *reinterpret_cast<const float2*>(&bias[col])
                             : make_float2(0.f, 0.f);
            const float v0 = acc[mi][ni][0] + b2.x, v1 = acc[mi][ni][1] + b2.y;
            const float v2 = acc[mi][ni][2] + b2.x, v3 = acc[mi][ni][3] + b2.y;
            if (Chi) {
                const __nv_bfloat16 h0 = __float2bfloat16(v0), h1 = __float2bfloat16(v1);
                const __nv_bfloat16 h2 = __float2bfloat16(v2), h3 = __float2bfloat16(v3);
                *reinterpret_cast<uint32_t*>(&Chi[(size_t)row1 * N + col]) = pack_hi(v0, v1);
                *reinterpret_cast<uint32_t*>(&Chi[(size_t)(row1 + 8) * N + col]) = pack_hi(v2, v3);
                *reinterpret_cast<uint32_t*>(&Clo[(size_t)row1 * N + col]) = pack_lo(v0, v1, h0, h1);
                *reinterpret_cast<uint32_t*>(&Clo[(size_t)(row1 + 8) * N + col]) = pack_lo(v2, v3, h2, h3);
            } else {
                *reinterpret_cast<float2*>(&C[(size_t)row1 * N + col]) = make_float2(v0, v1);
                *reinterpret_cast<float2*>(&C[(size_t)(row1 + 8) * N + col]) = make_float2(v2, v3);
            }
        }
    }
}

// ---------------------------------------------------------------------------
// Tensor-core flash attention, software-pipelined K/V prefetch.
// BM=128 q rows/CTA, BN=64 kv tile, 8 warps. Writes Ch/Cl directly.
// ---------------------------------------------------------------------------
#define AT_QH   0
#define AT_QL   32768
#define AT_KH   65536
#define AT_KL   81920
#define AT_VH   98304
#define AT_VL   114688
#define AT_PH   131072
#define AT_PL   147456
#define AT_WMAX 163840
#define AT_WSUM (AT_WMAX + 1024)
#define AT_M    (AT_WSUM + 1024)
#define AT_L    (AT_M + 512)
#define AT_CF   (AT_L + 512)
#define ATT_SMEM (AT_CF + 512)   // 167424 bytes

__device__ __forceinline__ void attn_load_K(uint32_t sb, const __nv_bfloat16* QKh,
                                            const __nv_bfloat16* QKl, int j0,
                                            int kcol, int bz, int tid)
{
#pragma unroll
    for (int t = 0; t < 2; ++t)
#pragma unroll
        for (int i = 0; i < 2; ++i) {
            const int u = tid + i * 256;
            const int r = u >> 3, cu = u & 7;
            const size_t grow = (size_t)(j0 + r) * 2 + bz;
            const size_t eoff = (grow * H3 + kcol + t * 64 + cu * 8) * 2;
            const uint32_t off = SWZ(r * 128 + cu * 16);
            cp16(sb + AT_KH + t * 8192 + off, (const char*)QKh + eoff);
            cp16(sb + AT_KL + t * 8192 + off, (const char*)QKl + eoff);
        }
}
__device__ __forceinline__ void attn_load_V(uint32_t sb, const __nv_bfloat16* Vth,
                                            const __nv_bfloat16* Vtl, int j0,
                                            int bh, int tid)
{
#pragma unroll
    for (int i = 0; i < 4; ++i) {
        const int u = tid + i * 256;
        const int r = u >> 3, cu = u & 7;
        const size_t eoff = (((size_t)bh * DHEAD + r) * S_LEN + j0 + cu * 8) * 2;
        const uint32_t off = SWZ(r * 128 + cu * 16);
        cp16(sb + AT_VH + off, (const char*)Vth + eoff);
        cp16(sb + AT_VL + off, (const char*)Vtl + eoff);
    }
}

__global__ __launch_bounds__(256) void attn_mma(
    const __nv_bfloat16* __restrict__ QKh, const __nv_bfloat16* __restrict__ QKl,
    const __nv_bfloat16* __restrict__ Vth, const __nv_bfloat16* __restrict__ Vtl,
    const unsigned char* __restrict__ pmask,
    __nv_bfloat16* __restrict__ Ch, __nv_bfloat16* __restrict__ Cl)
{
    extern __shared__ char smem[];
    const uint32_t sb = smem_u32(smem);
    float* warpmax = reinterpret_cast<float*>(smem + AT_WMAX);
    float* warpsum = reinterpret_cast<float*>(smem + AT_WSUM);
    float* m_sm    = reinterpret_cast<float*>(smem + AT_M);
    float* l_sm    = reinterpret_cast<float*>(smem + AT_L);
    float* cf_sm   = reinterpret_cast<float*>(smem + AT_CF);

    const int tid = threadIdx.x, warp = tid >> 5, lane = tid & 31;
    const int wm = warp >> 1, wn = warp & 1;
    const int qt = blockIdx.x, head = blockIdx.y, bz = blockIdx.z;
    const int q0 = qt * 128;
    const int qcol = head * 384, kcol = qcol + 128;
    const int bh = bz * NHEADS + head;
    const int ntiles = 2 * qt + 2;

    // ---- prologue: commit Q, K0, V0 as three groups ----
#pragma unroll
    for (int t = 0; t < 2; ++t) {
#pragma unroll
        for (int i = 0; i < 4; ++i) {
            const int u = tid + i * 256;
            const int r = u >> 3, cu = u & 7;
            const size_t grow = (size_t)(q0 + r) * 2 + bz;
            const size_t eoff = (grow * H3 + qcol + t * 64 + cu * 8) * 2;
            const uint32_t off = SWZ(r * 128 + cu * 16);
            cp16(sb + AT_QH + t * 16384 + off, (const char*)QKh + eoff);
            cp16(sb + AT_QL + t * 16384 + off, (const char*)QKl + eoff);
        }
    }
    if (tid < 128) { m_sm[tid] = -1e30f; l_sm[tid] = 0.f; }
    asm volatile("cp.async.commit_group;\n" ::: "memory");
    attn_load_K(sb, QKh, QKl, 0, kcol, bz, tid);
    asm volatile("cp.async.commit_group;\n" ::: "memory");
    attn_load_V(sb, Vth, Vtl, 0, bh, tid);
    asm volatile("cp.async.commit_group;\n" ::: "memory");

    const int a_r  = (lane & 7) + ((lane >> 3) & 1) * 8;
    const int a_kb = lane >> 4;
    const int b_r  = (lane & 7) + (lane >> 4) * 8;
    const int b_kb = (lane >> 3) & 1;
    const int r0   = lane >> 2;
    const int c0   = (lane & 3) * 2;

    float oacc[2][8][4];
#pragma unroll
    for (int mi = 0; mi < 2; ++mi)
#pragma unroll
        for (int ni = 0; ni < 8; ++ni)
#pragma unroll
            for (int e = 0; e < 4; ++e) oacc[mi][ni][e] = 0.f;

    for (int jt = 0; jt < ntiles; ++jt) {
        const int j0 = jt * 64;

        asm volatile("cp.async.wait_group 1;\n" ::: "memory");  // K(jt) ready
        __syncthreads();   // A

        // ---- S-phase: S = Q K^T (128x64x128, split-bf16) ----
        float sacc[2][4][4];
#pragma unroll
        for (int mi = 0; mi < 2; ++mi)
#pragma unroll
            for (int ni = 0; ni < 4; ++ni)
#pragma unroll
                for (int e = 0; e < 4; ++e) sacc[mi][ni][e] = 0.f;

#pragma unroll
        for (int kk = 0; kk < 8; ++kk) {
            const int t = kk >> 2, kby = (kk & 3) * 32;
            uint32_t qh[2][4], ql[2][4], kh[4][2], kl[4][2];
#pragma unroll
            for (int mi = 0; mi < 2; ++mi) {
                const int row = wm * 32 + mi * 16 + a_r;
                const uint32_t off = SWZ(row * 128 + kby + a_kb * 16);
                ldm_x4(sb + AT_QH + t * 16384 + off, qh[mi][0], qh[mi][1], qh[mi][2], qh[mi][3]);
                ldm_x4(sb + AT_QL + t * 16384 + off, ql[mi][0], ql[mi][1], ql[mi][2], ql[mi][3]);
            }
#pragma unroll
            for (int p = 0; p < 2; ++p) {
                const int row = wn * 32 + p * 16 + b_r;
                const uint32_t off = SWZ(row * 128 + kby + b_kb * 16);
                ldm_x4(sb + AT_KH + t * 8192 + off,
                       kh[2 * p][0], kh[2 * p][1], kh[2 * p + 1][0], kh[2 * p + 1][1]);
                ldm_x4(sb + AT_KL + t * 8192 + off,
                       kl[2 * p][0], kl[2 * p][1], kl[2 * p + 1][0], kl[2 * p + 1][1]);
            }
#pragma unroll
            for (int mi = 0; mi < 2; ++mi)
#pragma unroll
                for (int ni = 0; ni < 4; ++ni) {
                    mma16816(sacc[mi][ni], qh[mi], kh[ni]);
                    mma16816(sacc[mi][ni], qh[mi], kl[ni]);
                    mma16816(sacc[mi][ni], ql[mi], kh[ni]);
                }
        }

        // ---- scale + mask + per-warp row max ----
#pragma unroll
        for (int mi = 0; mi < 2; ++mi) {
            const int lr = wm * 32 + mi * 16 + r0;
            const int gr0 = q0 + lr, gr1 = gr0 + 8;
            float rm0 = -1e30f, rm1 = -1e30f;
#pragma unroll
            for (int ni = 0; ni < 4; ++ni) {
                const int gc = j0 + wn * 32 + ni * 8 + c0;
                const uchar2 mA = *reinterpret_cast<const uchar2*>(
                    &pmask[((size_t)bz * S_LEN + gr0) * S_LEN + gc]);
                const uchar2 mB = *reinterpret_cast<const uchar2*>(
                    &pmask[((size_t)bz * S_LEN + gr1) * S_LEN + gc]);
                float* s = sacc[mi][ni];
                s[0] = (gc     > gr0 || mA.x) ? -10000.f : s[0] * INV_NORM;
                s[1] = (gc + 1 > gr0 || mA.y) ? -10000.f : s[1] * INV_NORM;
                s[2] = (gc     > gr1 || mB.x) ? -10000.f : s[2] * INV_NORM;
                s[3] = (gc + 1 > gr1 || mB.y) ? -10000.f : s[3] * INV_NORM;
                rm0 = fmaxf(rm0, fmaxf(s[0], s[1]));
                rm1 = fmaxf(rm1, fmaxf(s[2], s[3]));
            }
            rm0 = fmaxf(rm0, __shfl_xor_sync(0xffffffffu, rm0, 1));
            rm0 = fmaxf(rm0, __shfl_xor_sync(0xffffffffu, rm0, 2));
            rm1 = fmaxf(rm1, __shfl_xor_sync(0xffffffffu, rm1, 1));
            rm1 = fmaxf(rm1, __shfl_xor_sync(0xffffffffu, rm1, 2));
            if ((lane & 3) == 0) {
                warpmax[wn * 128 + lr]     = rm0;
                warpmax[wn * 128 + lr + 8] = rm1;
            }
        }
        __syncthreads();   // B: done reading K, warpmax visible

        // prefetch K(jt+1) into the now-free K buffer
        if (jt + 1 < ntiles) attn_load_K(sb, QKh, QKl, j0 + 64, kcol, bz, tid);
        asm volatile("cp.async.commit_group;\n" ::: "memory");

        if (tid < 128) {
            const float mold = m_sm[tid];
            const float mnew = fmaxf(mold, fmaxf(warpmax[tid], warpmax[128 + tid]));
            m_sm[tid]  = mnew;
            cf_sm[tid] = __expf(mold - mnew);
        }
        __syncthreads();   // C

        // ---- exp + store P (hi/lo) + row sums ----
#pragma unroll
        for (int mi = 0; mi < 2; ++mi) {
            const int lr = wm * 32 + mi * 16 + r0;
            const float m0v = m_sm[lr], m1v = m_sm[lr + 8];
            float rs0 = 0.f, rs1 = 0.f;
#pragma unroll
            for (int ni = 0; ni < 4; ++ni) {
                float* s = sacc[mi][ni];
                const float p0 = __expf(s[0] - m0v);
                const float p1 = __expf(s[1] - m0v);
                const float p2 = __expf(s[2] - m1v);
                const float p3 = __expf(s[3] - m1v);
                rs0 += p0 + p1;
                rs1 += p2 + p3;
                const int cbyte = (wn * 32 + ni * 8 + c0) * 2;
                const __nv_bfloat16 h0 = __float2bfloat16(p0);
                const __nv_bfloat16 h1 = __float2bfloat16(p1);
                const __nv_bfloat16 h2 = __float2bfloat16(p2);
                const __nv_bfloat16 h3 = __float2bfloat16(p3);
                *reinterpret_cast<uint32_t*>(smem + AT_PH + SWZ(lr * 128 + cbyte)) =
                    pack_hi(p0, p1);
                *reinterpret_cast<uint32_t*>(smem + AT_PH + SWZ((lr + 8) * 128 + cbyte)) =
                    pack_hi(p2, p3);
                *reinterpret_cast<uint32_t*>(smem + AT_PL + SWZ(lr * 128 + cbyte)) =
                    pack_lo(p0, p1, h0, h1);
                *reinterpret_cast<uint32_t*>(smem + AT_PL + SWZ((lr + 8) * 128 + cbyte)) =
                    pack_lo(p2, p3, h2, h3);
            }
            rs0 += __shfl_xor_sync(0xffffffffu, rs0, 1);
            rs0 += __shfl_xor_sync(0xffffffffu, rs0, 2);
            rs1 += __shfl_xor_sync(0xffffffffu, rs1, 1);
            rs1 += __shfl_xor_sync(0xffffffffu, rs1, 2);
            if ((lane & 3) == 0) {
                warpsum[wn * 128 + lr]     = rs0;
                warpsum[wn * 128 + lr + 8] = rs1;
            }
        }
        __syncthreads();   // D: P + warpsum visible
        if (tid < 128)
            l_sm[tid] = l_sm[tid] * cf_sm[tid] + warpsum[tid] + warpsum[128 + tid];

        asm volatile("cp.async.wait_group 1;\n" ::: "memory");  // V(jt) ready
        __syncthreads();   // F

        // ---- O-phase: O = O*cf + P @ Vt (128x128x64, split-bf16) ----
#pragma unroll
        for (int mi = 0; mi < 2; ++mi) {
            const int lr = wm * 32 + mi * 16 + r0;
            const float cfa = cf_sm[lr], cfb = cf_sm[lr + 8];
#pragma unroll
            for (int ni = 0; ni < 8; ++ni) {
                oacc[mi][ni][0] *= cfa; oacc[mi][ni][1] *= cfa;
                oacc[mi][ni][2] *= cfb; oacc[mi][ni][3] *= cfb;
            }
        }
#pragma unroll
        for (int kk = 0; kk < 4; ++kk) {
            const int kby = kk * 32;
            uint32_t ph[2][4], pl[2][4], vh[8][2], vl[8][2];
#pragma unroll
            for (int mi = 0; mi < 2; ++mi) {
                const int row = wm * 32 + mi * 16 + a_r;
                const uint32_t off = SWZ(row * 128 + kby + a_kb * 16);
                ldm_x4(sb + AT_PH + off, ph[mi][0], ph[mi][1], ph[mi][2], ph[mi][3]);
                ldm_x4(sb + AT_PL + off, pl[mi][0], pl[mi][1], pl[mi][2], pl[mi][3]);
            }
#pragma unroll
            for (int p = 0; p < 4; ++p) {
                const int row = wn * 64 + p * 16 + b_r;
                const uint32_t off = SWZ(row * 128 + kby + b_kb * 16);
                ldm_x4(sb + AT_VH + off,
                       vh[2 * p][0], vh[2 * p][1], vh[2 * p + 1][0], vh[2 * p + 1][1]);
                ldm_x4(sb + AT_VL + off,
                       vl[2 * p][0], vl[2 * p][1], vl[2 * p + 1][0], vl[2 * p + 1][1]);
            }
#pragma unroll
            for (int mi = 0; mi < 2; ++mi)
#pragma unroll
                for (int ni = 0; ni < 8; ++ni) {
                    mma16816(oacc[mi][ni], ph[mi], vh[ni]);
                    mma16816(oacc[mi][ni], ph[mi], vl[ni]);
                    mma16816(oacc[mi][ni], pl[mi], vh[ni]);
                }
        }
        __syncthreads();   // E: done reading V and P

        // prefetch V(jt+1) into the now-free V buffer
        if (jt + 1 < ntiles) attn_load_V(sb, Vth, Vtl, j0 + 64, bh, tid);
        asm volatile("cp.async.commit_group;\n" ::: "memory");
    }

    // ---- epilogue: normalize, split to bf16 hi/lo, write Ch/Cl ----
#pragma unroll
    for (int mi = 0; mi < 2; ++mi) {
        const int lr = wm * 32 + mi * 16 + r0;
        const float il0 = 1.0f / l_sm[lr];
        const float il1 = 1.0f / l_sm[lr + 8];
        const size_t grow0 = (size_t)(q0 + lr) * 2 + bz;
        const size_t grow1 = grow0 + 16;
#pragma unroll
        for (int ni = 0; ni < 8; ++ni) {
            const int col = head * DHEAD + wn * 64 + ni * 8 + c0;
            const float o0 = oacc[mi][ni][0] * il0, o1 = oacc[mi][ni][1] * il0;
            const float o2 = oacc[mi][ni][2] * il1, o3 = oacc[mi][ni][3] * il1;
            const __nv_bfloat16 h0 = __float2bfloat16(o0), h1 = __float2bfloat16(o1);
            const __nv_bfloat16 h2 = __float2bfloat16(o2), h3 = __float2bfloat16(o3);
            *reinterpret_cast<uint32_t*>(&Ch[grow0 * HID + col]) = pack_hi(o0, o1);
            *reinterpret_cast<uint32_t*>(&Ch[grow1 * HID + col]) = pack_hi(o2, o3);
            *reinterpret_cast<uint32_t*>(&Cl[grow0 * HID + col]) = pack_lo(o0, o1, h0, h1);
            *reinterpret_cast<uint32_t*>(&Cl[grow1 * HID + col]) = pack_lo(o2, o3, h2, h3);
        }
    }
}

// Tail: copy proj_bias after the main output if the harness expects it
__global__ void tail_bias_kernel(const float* __restrict__ bias,
                                 float* __restrict__ out, int n)
{
    const int i = blockIdx.x * blockDim.x + threadIdx.x;
    if (i < n) out[(size_t)NROWS * HID + i] = bias[i];
}

// ---------------------------------------------------------------------------
extern "C" void kernel_launch(void* const* d_in, const int* in_sizes, int n_in,
                              void* d_out, int out_size)
{
    const float*         hidden  = (const float*)d_in[0];
    const unsigned char* amask   = (const unsigned char*)d_in[1];
    const float*         qkv_w   = (const float*)d_in[2];
    const float*         qkv_b   = (const float*)d_in[3];
    const float*         proj_w  = (const float*)d_in[4];
    const float*         proj_b  = (const float*)d_in[5];
    float*               out     = (float*)d_out;

    __nv_bfloat16 *Ah, *Al, *Wqh, *Wql, *Wph, *Wpl, *Ch, *Cl, *QKh, *QKl, *Vth, *Vtl;
    cudaGetSymbolAddress((void**)&Ah,   g_Ah);
    cudaGetSymbolAddress((void**)&Al,   g_Al);
    cudaGetSymbolAddress((void**)&Wqh,  g_Wqh);
    cudaGetSymbolAddress((void**)&Wql,  g_Wql);
    cudaGetSymbolAddress((void**)&Wph,  g_Wph);
    cudaGetSymbolAddress((void**)&Wpl,  g_Wpl);
    cudaGetSymbolAddress((void**)&Ch,   g_Ch);
    cudaGetSymbolAddress((void**)&Cl,   g_Cl);
    cudaGetSymbolAddress((void**)&QKh,  g_qkvh);
    cudaGetSymbolAddress((void**)&QKl,  g_qkvl);
    cudaGetSymbolAddress((void**)&Vth,  g_Vth);
    cudaGetSymbolAddress((void**)&Vtl,  g_Vtl);

    cudaFuncSetAttribute(gemm_mma,
                         cudaFuncAttributeMaxDynamicSharedMemorySize, GSM_BYTES);
    cudaFuncSetAttribute(attn_mma,
                         cudaFuncAttributeMaxDynamicSharedMemorySize, ATT_SMEM);

    // 0) input conversions
    {
        const int n4 = (NROWS * HID) / 4;
        split_kernel<<<(n4 + 255) / 256, 256>>>(hidden, Ah, Al, n4);
        dim3 tb(32, 8);
        tsplit_kernel<<<dim3(H3 / 32, HID / 32), tb>>>(qkv_w, Wqh, Wql, HID, H3);
        tsplit_kernel<<<dim3(HID / 32, HID / 32), tb>>>(proj_w, Wph, Wpl, HID, HID);
    }
    // 1) QKV GEMM (mma.sync), split epilogue -> qkvh/qkvl directly
    {
        dim3 grid(H3 / 128, NROWS / 128);
        gemm_mma<<<grid, 256, GSM_BYTES>>>(Ah, Al, Wqh, Wql, qkv_b, nullptr,
                                           QKh, QKl, NROWS, H3, HID);
    }
    // 2) V transpose (bf16 pass-through)
    {
        dim3 tb(32, 8);
        vtrans_kernel<<<dim3(S_LEN / 32, DHEAD / 32, BATCH * NHEADS), tb>>>(
            QKh, QKl, Vth, Vtl);
    }
    // 3) Attention (tensor cores, pipelined) -> Ch/Cl
    {
        dim3 grid(S_LEN / 128, NHEADS, BATCH);
        attn_mma<<<grid, 256, ATT_SMEM>>>(QKh, QKl, Vth, Vtl, amask, Ch, Cl);
    }
    // 4) Output projection (mma.sync) -> fp32 out
    {
        dim3 grid(HID / 128, NROWS / 128);
        gemm_mma<<<grid, 256, GSM_BYTES>>>(Ch, Cl, Wph, Wpl, nullptr, out,
                                           nullptr, nullptr, NROWS, HID, HID);
    }
    // 5) Optional bias tail
    const long long main_elems = (long long)NROWS * HID;
    const long long extra = (long long)out_size - main_elems;
    if (extra > 0) {
        const int n = (int)extra;
        tail_bias_kernel<<<(n + 255) / 256, 256>>>(proj_b, out, n);
    }
}

// round 7
// speedup vs baseline: 3.6495x; 1.0791x over previous
#include <cuda_runtime.h>
#include <cuda_bf16.h>
#include <cstdint>

// Problem constants (fixed by the reference setup)
#define S_LEN   2048
#define BATCH   2
#define NHEADS  16
#define DHEAD   128
#define HID     2048
#define H3      6144
#define NROWS   (S_LEN * BATCH)       // 4096
#define INV_NORM 0.08838834764831845f // 1/sqrt(128)

// ---------------- device-global scratch (no cudaMalloc allowed) ----------------
__device__ __nv_bfloat16 g_Ah[(size_t)NROWS * HID];
__device__ __nv_bfloat16 g_Al[(size_t)NROWS * HID];
__device__ __nv_bfloat16 g_Wqh[(size_t)H3 * HID];      // qkv_w^T [6144,2048]
__device__ __nv_bfloat16 g_Wql[(size_t)H3 * HID];
__device__ __nv_bfloat16 g_Wph[(size_t)HID * HID];     // proj_w^T [2048,2048]
__device__ __nv_bfloat16 g_Wpl[(size_t)HID * HID];
__device__ __nv_bfloat16 g_Ch[(size_t)NROWS * HID];    // attention out hi
__device__ __nv_bfloat16 g_Cl[(size_t)NROWS * HID];    // attention out lo
__device__ __nv_bfloat16 g_qkvh[(size_t)NROWS * H3];   // qkv split hi (gemm writes)
__device__ __nv_bfloat16 g_qkvl[(size_t)NROWS * H3];   // qkv split lo
__device__ __nv_bfloat16 g_Vth[(size_t)BATCH * NHEADS * DHEAD * S_LEN]; // V^T [b][h][d][s]
__device__ __nv_bfloat16 g_Vtl[(size_t)BATCH * NHEADS * DHEAD * S_LEN];

// ---------------- helpers (sm_80-level PTX only) ----------------
__device__ __forceinline__ uint32_t smem_u32(const void* p) {
    uint32_t a;
    asm("{ .reg .u64 t; cvta.to.shared.u64 t, %1; cvt.u32.u64 %0, t; }" : "=r"(a) : "l"(p));
    return a;
}
#define SWZ(o) ((o) ^ (((o) >> 3) & 0x70))

__device__ __forceinline__ void cp16(uint32_t dst, const void* src) {
    asm volatile("cp.async.cg.shared.global [%0], [%1], 16;\n" :: "r"(dst), "l"(src));
}
__device__ __forceinline__ void ldm_x4(uint32_t addr, uint32_t& r0, uint32_t& r1,
                                       uint32_t& r2, uint32_t& r3) {
    asm volatile("ldmatrix.sync.aligned.m8n8.x4.shared.b16 {%0,%1,%2,%3}, [%4];"
                 : "=r"(r0), "=r"(r1), "=r"(r2), "=r"(r3) : "r"(addr));
}
__device__ __forceinline__ void mma16816(float* c, const uint32_t* a, const uint32_t* b) {
    asm volatile(
        "mma.sync.aligned.m16n8k16.row.col.f32.bf16.bf16.f32 "
        "{%0,%1,%2,%3}, {%4,%5,%6,%7}, {%8,%9}, {%0,%1,%2,%3};"
        : "+f"(c[0]), "+f"(c[1]), "+f"(c[2]), "+f"(c[3])
        : "r"(a[0]), "r"(a[1]), "r"(a[2]), "r"(a[3]), "r"(b[0]), "r"(b[1]));
}
__device__ __forceinline__ uint32_t pack_hi(float x, float y) {
    __nv_bfloat162 t(__float2bfloat16(x), __float2bfloat16(y));
    return *reinterpret_cast<uint32_t*>(&t);
}
__device__ __forceinline__ uint32_t pack_lo(float x, float y,
                                            __nv_bfloat16 hx, __nv_bfloat16 hy) {
    __nv_bfloat162 t(__float2bfloat16(x - __bfloat162float(hx)),
                     __float2bfloat16(y - __bfloat162float(hy)));
    return *reinterpret_cast<uint32_t*>(&t);
}

// ---------------------------------------------------------------------------
// Conversion kernels
// ---------------------------------------------------------------------------
__global__ __launch_bounds__(256) void split_kernel(
    const float* __restrict__ x, __nv_bfloat16* __restrict__ hi,
    __nv_bfloat16* __restrict__ lo, int n4)
{
    const int i = blockIdx.x * blockDim.x + threadIdx.x;
    if (i < n4) {
        float4 v = reinterpret_cast<const float4*>(x)[i];
        float f[4] = {v.x, v.y, v.z, v.w};
        __nv_bfloat16 h[4], l[4];
#pragma unroll
        for (int j = 0; j < 4; ++j) {
            h[j] = __float2bfloat16(f[j]);
            l[j] = __float2bfloat16(f[j] - __bfloat162float(h[j]));
        }
        reinterpret_cast<__nv_bfloat162*>(hi)[i * 2 + 0] = __nv_bfloat162(h[0], h[1]);
        reinterpret_cast<__nv_bfloat162*>(hi)[i * 2 + 1] = __nv_bfloat162(h[2], h[3]);
        reinterpret_cast<__nv_bfloat162*>(lo)[i * 2 + 0] = __nv_bfloat162(l[0], l[1]);
        reinterpret_cast<__nv_bfloat162*>(lo)[i * 2 + 1] = __nv_bfloat162(l[2], l[3]);
    }
}

// Transpose + split: W [K,N] fp32 -> Th/Tl [N,K] bf16
__global__ void tsplit_kernel(const float* __restrict__ W,
                              __nv_bfloat16* __restrict__ Th,
                              __nv_bfloat16* __restrict__ Tl, int K, int N)
{
    __shared__ float t[32][33];
    const int x = blockIdx.x * 32 + threadIdx.x;
    const int y0 = blockIdx.y * 32;
#pragma unroll
    for (int j = threadIdx.y; j < 32; j += 8)
        t[j][threadIdx.x] = W[(size_t)(y0 + j) * N + x];
    __syncthreads();
    const int kx = y0 + threadIdx.x;
#pragma unroll
    for (int j = threadIdx.y; j < 32; j += 8) {
        const float v = t[threadIdx.x][j];
        const __nv_bfloat16 h = __float2bfloat16(v);
        const __nv_bfloat16 l = __float2bfloat16(v - __bfloat162float(h));
        const size_t o = (size_t)(blockIdx.x * 32 + j) * K + kx;
        Th[o] = h;
        Tl[o] = l;
    }
}

// V transpose (bf16 hi/lo pass-through): qkv split v-region -> Vt [b][h][d][s]
__global__ void vtrans_kernel(const __nv_bfloat16* __restrict__ qh,
                              const __nv_bfloat16* __restrict__ ql,
                              __nv_bfloat16* __restrict__ Vth,
                              __nv_bfloat16* __restrict__ Vtl)
{
    __shared__ __nv_bfloat16 th[32][33], tl[32][33];
    const int s0 = blockIdx.x * 32, d0 = blockIdx.y * 32;
    const int bh = blockIdx.z;
    const int b = bh >> 4, h = bh & 15;
    const int col = h * 384 + 256 + d0 + threadIdx.x;
#pragma unroll
    for (int j = threadIdx.y; j < 32; j += 8) {
        const size_t grow = (size_t)(s0 + j) * 2 + b;
        th[j][threadIdx.x] = qh[grow * H3 + col];
        tl[j][threadIdx.x] = ql[grow * H3 + col];
    }
    __syncthreads();
#pragma unroll
    for (int j = threadIdx.y; j < 32; j += 8) {
        const size_t o = ((size_t)bh * DHEAD + d0 + j) * S_LEN + s0 + threadIdx.x;
        Vth[o] = th[threadIdx.x][j];
        Vtl[o] = tl[threadIdx.x][j];
    }
}

// ---------------------------------------------------------------------------
// mma.sync split-bf16 GEMM, high-occupancy version:
// CTA tile 128x64, BK=64, 2-stage pipeline (48KB/stage), 2 CTAs/SM.
// 8 warps in 4m x 2n grid, warp tile 32x32.
// Optional split epilogue (Chi/Clo bf16) or fp32 C (+bias).
// ---------------------------------------------------------------------------
#define GA_T   16384                 // A tile: 128 rows x 128B
#define GB_T   8192                  // B tile:  64 rows x 128B
#define GSTG   (2 * GA_T + 2 * GB_T) // 49152
#define GSM_BYTES (2 * GSTG)         // 98304

template <int ROWS>
__device__ __forceinline__ void load_tile_r(uint32_t sbase, const __nv_bfloat16* g,
                                            int row0, int k0, int K)
{
    const int tid = threadIdx.x;
#pragma unroll
    for (int i = 0; i < ROWS / 32; ++i) {   // ROWS*8 units / 256 threads
        const int u = tid + i * 256;
        const int r = u >> 3, cu = u & 7;
        const uint32_t dst = sbase + SWZ(r * 128 + cu * 16);
        const char* src = (const char*)g + ((size_t)(row0 + r) * K + k0) * 2 + cu * 16;
        cp16(dst, src);
    }
}

__device__ __forceinline__ void gemm_load_stage(
    uint32_t bb, const __nv_bfloat16* Ah, const __nv_bfloat16* Al,
    const __nv_bfloat16* Bh, const __nv_bfloat16* Bl, int m0, int n0, int k0, int K)
{
    load_tile_r<128>(bb,                 Ah, m0, k0, K);
    load_tile_r<128>(bb + GA_T,          Al, m0, k0, K);
    load_tile_r<64>( bb + 2 * GA_T,      Bh, n0, k0, K);
    load_tile_r<64>( bb + 2 * GA_T + GB_T, Bl, n0, k0, K);
}

__global__ __launch_bounds__(256, 2) void gemm_mma(
    const __nv_bfloat16* __restrict__ Ah, const __nv_bfloat16* __restrict__ Al,
    const __nv_bfloat16* __restrict__ Bh, const __nv_bfloat16* __restrict__ Bl,
    const float* __restrict__ bias, float* __restrict__ C,
    __nv_bfloat16* __restrict__ Chi, __nv_bfloat16* __restrict__ Clo,
    int M, int N, int K)
{
    extern __shared__ char smem[];
    const uint32_t sb = smem_u32(smem);
    const int tid  = threadIdx.x;
    const int warp = tid >> 5, lane = tid & 31;
    const int wm = warp >> 1, wn = warp & 1;     // 4m x 2n warp grid
    const int n0 = blockIdx.x * 64, m0 = blockIdx.y * 128;

    float acc[2][4][4];
#pragma unroll
    for (int mi = 0; mi < 2; ++mi)
#pragma unroll
        for (int ni = 0; ni < 4; ++ni)
#pragma unroll
            for (int e = 0; e < 4; ++e) acc[mi][ni][e] = 0.f;

    const int NC = K / 64;
    gemm_load_stage(sb, Ah, Al, Bh, Bl, m0, n0, 0, K);
    asm volatile("cp.async.commit_group;\n" ::: "memory");

    const int a_r  = (lane & 7) + ((lane >> 3) & 1) * 8;
    const int a_kb = lane >> 4;
    const int b_r  = (lane & 7) + (lane >> 4) * 8;
    const int b_kb = (lane >> 3) & 1;

    for (int c = 0; c < NC; ++c) {
        asm volatile("cp.async.wait_group 0;\n" ::: "memory");
        __syncthreads();   // stage c ready; all warps done reading stage c-1's buffer
        if (c + 1 < NC)
            gemm_load_stage(sb + ((c + 1) & 1) * GSTG, Ah, Al, Bh, Bl,
                            m0, n0, (c + 1) * 64, K);
        asm volatile("cp.async.commit_group;\n" ::: "memory");

        const uint32_t bb   = sb + (c & 1) * GSTG;
        const uint32_t aihB = bb;
        const uint32_t ailB = bb + GA_T;
        const uint32_t bihB = bb + 2 * GA_T;
        const uint32_t bilB = bb + 2 * GA_T + GB_T;

#pragma unroll
        for (int kk = 0; kk < 4; ++kk) {
            const int kby = kk * 32;
            uint32_t ah[2][4], al[2][4], bh[4][2], bl[4][2];
#pragma unroll
            for (int mi = 0; mi < 2; ++mi) {
                const int row = wm * 32 + mi * 16 + a_r;
                const uint32_t off = SWZ(row * 128 + kby + a_kb * 16);
                ldm_x4(aihB + off, ah[mi][0], ah[mi][1], ah[mi][2], ah[mi][3]);
                ldm_x4(ailB + off, al[mi][0], al[mi][1], al[mi][2], al[mi][3]);
            }
#pragma unroll
            for (int p = 0; p < 2; ++p) {
                const int row = wn * 32 + p * 16 + b_r;
                const uint32_t off = SWZ(row * 128 + kby + b_kb * 16);
                ldm_x4(bihB + off, bh[2 * p][0], bh[2 * p][1], bh[2 * p + 1][0], bh[2 * p + 1][1]);
                ldm_x4(bilB + off, bl[2 * p][0], bl[2 * p][1], bl[2 * p + 1][0], bl[2 * p + 1][1]);
            }
#pragma unroll
            for (int mi = 0; mi < 2; ++mi)
#pragma unroll
                for (int ni = 0; ni < 4; ++ni) {
                    mma16816(acc[mi][ni], ah[mi], bh[ni]);
                    mma16816(acc[mi][ni], ah[mi], bl[ni]);
                    mma16816(acc[mi][ni], al[mi], bh[ni]);
                }
        }
    }

    const int r0 = lane >> 2;
    const int c0 = (lane & 3) * 2;
#pragma unroll
    for (int mi = 0; mi < 2; ++mi) {
#pragma unroll
        for (int ni = 0; ni < 4; ++ni) {
            const int col  = n0 + wn * 32 + ni * 8 + c0;
            const int row1 = m0 + wm * 32 + mi * 16 + r0;
            float2 b2 = bias ? *reinterpret_cast<const float2*>(&bias[col])
                             : make_float2(0.f, 0.f);
            const float v0 = acc[mi][ni][0] + b2.x, v1 = acc[mi][ni][1] + b2.y;
            const float v2 = acc[mi][ni][2] + b2.x, v3 = acc[mi][ni][3] + b2.y;
            if (Chi) {
                const __nv_bfloat16 h0 = __float2bfloat16(v0), h1 = __float2bfloat16(v1);
                const __nv_bfloat16 h2 = __float2bfloat16(v2), h3 = __float2bfloat16(v3);
                *reinterpret_cast<uint32_t*>(&Chi[(size_t)row1 * N + col]) = pack_hi(v0, v1);
                *reinterpret_cast<uint32_t*>(&Chi[(size_t)(row1 + 8) * N + col]) = pack_hi(v2, v3);
                *reinterpret_cast<uint32_t*>(&Clo[(size_t)row1 * N + col]) = pack_lo(v0, v1, h0, h1);
                *reinterpret_cast<uint32_t*>(&Clo[(size_t)(row1 + 8) * N + col]) = pack_lo(v2, v3, h2, h3);
            } else {
                *reinterpret_cast<float2*>(&C[(size_t)row1 * N + col]) = make_float2(v0, v1);
                *reinterpret_cast<float2*>(&C[(size_t)(row1 + 8) * N + col]) = make_float2(v2, v3);
            }
        }
    }
}

// ---------------------------------------------------------------------------
// Tensor-core flash attention, software-pipelined K/V prefetch (unchanged).
// BM=128 q rows/CTA, BN=64 kv tile, 8 warps. Writes Ch/Cl directly.
// ---------------------------------------------------------------------------
#define AT_QH   0
#define AT_QL   32768
#define AT_KH   65536
#define AT_KL   81920
#define AT_VH   98304
#define AT_VL   114688
#define AT_PH   131072
#define AT_PL   147456
#define AT_WMAX 163840
#define AT_WSUM (AT_WMAX + 1024)
#define AT_M    (AT_WSUM + 1024)
#define AT_L    (AT_M + 512)
#define AT_CF   (AT_L + 512)
#define ATT_SMEM (AT_CF + 512)   // 167424 bytes

__device__ __forceinline__ void attn_load_K(uint32_t sb, const __nv_bfloat16* QKh,
                                            const __nv_bfloat16* QKl, int j0,
                                            int kcol, int bz, int tid)
{
#pragma unroll
    for (int t = 0; t < 2; ++t)
#pragma unroll
        for (int i = 0; i < 2; ++i) {
            const int u = tid + i * 256;
            const int r = u >> 3, cu = u & 7;
            const size_t grow = (size_t)(j0 + r) * 2 + bz;
            const size_t eoff = (grow * H3 + kcol + t * 64 + cu * 8) * 2;
            const uint32_t off = SWZ(r * 128 + cu * 16);
            cp16(sb + AT_KH + t * 8192 + off, (const char*)QKh + eoff);
            cp16(sb + AT_KL + t * 8192 + off, (const char*)QKl + eoff);
        }
}
__device__ __forceinline__ void attn_load_V(uint32_t sb, const __nv_bfloat16* Vth,
                                            const __nv_bfloat16* Vtl, int j0,
                                            int bh, int tid)
{
#pragma unroll
    for (int i = 0; i < 4; ++i) {
        const int u = tid + i * 256;
        const int r = u >> 3, cu = u & 7;
        const size_t eoff = (((size_t)bh * DHEAD + r) * S_LEN + j0 + cu * 8) * 2;
        const uint32_t off = SWZ(r * 128 + cu * 16);
        cp16(sb + AT_VH + off, (const char*)Vth + eoff);
        cp16(sb + AT_VL + off, (const char*)Vtl + eoff);
    }
}

__global__ __launch_bounds__(256) void attn_mma(
    const __nv_bfloat16* __restrict__ QKh, const __nv_bfloat16* __restrict__ QKl,
    const __nv_bfloat16* __restrict__ Vth, const __nv_bfloat16* __restrict__ Vtl,
    const unsigned char* __restrict__ pmask,
    __nv_bfloat16* __restrict__ Ch, __nv_bfloat16* __restrict__ Cl)
{
    extern __shared__ char smem[];
    const uint32_t sb = smem_u32(smem);
    float* warpmax = reinterpret_cast<float*>(smem + AT_WMAX);
    float* warpsum = reinterpret_cast<float*>(smem + AT_WSUM);
    float* m_sm    = reinterpret_cast<float*>(smem + AT_M);
    float* l_sm    = reinterpret_cast<float*>(smem + AT_L);
    float* cf_sm   = reinterpret_cast<float*>(smem + AT_CF);

    const int tid = threadIdx.x, warp = tid >> 5, lane = tid & 31;
    const int wm = warp >> 1, wn = warp & 1;
    const int qt = blockIdx.x, head = blockIdx.y, bz = blockIdx.z;
    const int q0 = qt * 128;
    const int qcol = head * 384, kcol = qcol + 128;
    const int bh = bz * NHEADS + head;
    const int ntiles = 2 * qt + 2;

    // ---- prologue: commit Q, K0, V0 as three groups ----
#pragma unroll
    for (int t = 0; t < 2; ++t) {
#pragma unroll
        for (int i = 0; i < 4; ++i) {
            const int u = tid + i * 256;
            const int r = u >> 3, cu = u & 7;
            const size_t grow = (size_t)(q0 + r) * 2 + bz;
            const size_t eoff = (grow * H3 + qcol + t * 64 + cu * 8) * 2;
            const uint32_t off = SWZ(r * 128 + cu * 16);
            cp16(sb + AT_QH + t * 16384 + off, (const char*)QKh + eoff);
            cp16(sb + AT_QL + t * 16384 + off, (const char*)QKl + eoff);
        }
    }
    if (tid < 128) { m_sm[tid] = -1e30f; l_sm[tid] = 0.f; }
    asm volatile("cp.async.commit_group;\n" ::: "memory");
    attn_load_K(sb, QKh, QKl, 0, kcol, bz, tid);
    asm volatile("cp.async.commit_group;\n" ::: "memory");
    attn_load_V(sb, Vth, Vtl, 0, bh, tid);
    asm volatile("cp.async.commit_group;\n" ::: "memory");

    const int a_r  = (lane & 7) + ((lane >> 3) & 1) * 8;
    const int a_kb = lane >> 4;
    const int b_r  = (lane & 7) + (lane >> 4) * 8;
    const int b_kb = (lane >> 3) & 1;
    const int r0   = lane >> 2;
    const int c0   = (lane & 3) * 2;

    float oacc[2][8][4];
#pragma unroll
    for (int mi = 0; mi < 2; ++mi)
#pragma unroll
        for (int ni = 0; ni < 8; ++ni)
#pragma unroll
            for (int e = 0; e < 4; ++e) oacc[mi][ni][e] = 0.f;

    for (int jt = 0; jt < ntiles; ++jt) {
        const int j0 = jt * 64;

        asm volatile("cp.async.wait_group 1;\n" ::: "memory");  // K(jt) ready
        __syncthreads();   // A

        // ---- S-phase: S = Q K^T (128x64x128, split-bf16) ----
        float sacc[2][4][4];
#pragma unroll
        for (int mi = 0; mi < 2; ++mi)
#pragma unroll
            for (int ni = 0; ni < 4; ++ni)
#pragma unroll
                for (int e = 0; e < 4; ++e) sacc[mi][ni][e] = 0.f;

#pragma unroll
        for (int kk = 0; kk < 8; ++kk) {
            const int t = kk >> 2, kby = (kk & 3) * 32;
            uint32_t qh[2][4], ql[2][4], kh[4][2], kl[4][2];
#pragma unroll
            for (int mi = 0; mi < 2; ++mi) {
                const int row = wm * 32 + mi * 16 + a_r;
                const uint32_t off = SWZ(row * 128 + kby + a_kb * 16);
                ldm_x4(sb + AT_QH + t * 16384 + off, qh[mi][0], qh[mi][1], qh[mi][2], qh[mi][3]);
                ldm_x4(sb + AT_QL + t * 16384 + off, ql[mi][0], ql[mi][1], ql[mi][2], ql[mi][3]);
            }
#pragma unroll
            for (int p = 0; p < 2; ++p) {
                const int row = wn * 32 + p * 16 + b_r;
                const uint32_t off = SWZ(row * 128 + kby + b_kb * 16);
                ldm_x4(sb + AT_KH + t * 8192 + off,
                       kh[2 * p][0], kh[2 * p][1], kh[2 * p + 1][0], kh[2 * p + 1][1]);
                ldm_x4(sb + AT_KL + t * 8192 + off,
                       kl[2 * p][0], kl[2 * p][1], kl[2 * p + 1][0], kl[2 * p + 1][1]);
            }
#pragma unroll
            for (int mi = 0; mi < 2; ++mi)
#pragma unroll
                for (int ni = 0; ni < 4; ++ni) {
                    mma16816(sacc[mi][ni], qh[mi], kh[ni]);
                    mma16816(sacc[mi][ni], qh[mi], kl[ni]);
                    mma16816(sacc[mi][ni], ql[mi], kh[ni]);
                }
        }

        // ---- scale + mask + per-warp row max ----
#pragma unroll
        for (int mi = 0; mi < 2; ++mi) {
            const int lr = wm * 32 + mi * 16 + r0;
            const int gr0 = q0 + lr, gr1 = gr0 + 8;
            float rm0 = -1e30f, rm1 = -1e30f;
#pragma unroll
            for (int ni = 0; ni < 4; ++ni) {
                const int gc = j0 + wn * 32 + ni * 8 + c0;
                const uchar2 mA = *reinterpret_cast<const uchar2*>(
                    &pmask[((size_t)bz * S_LEN + gr0) * S_LEN + gc]);
                const uchar2 mB = *reinterpret_cast<const uchar2*>(
                    &pmask[((size_t)bz * S_LEN + gr1) * S_LEN + gc]);
                float* s = sacc[mi][ni];
                s[0] = (gc     > gr0 || mA.x) ? -10000.f : s[0] * INV_NORM;
                s[1] = (gc + 1 > gr0 || mA.y) ? -10000.f : s[1] * INV_NORM;
                s[2] = (gc     > gr1 || mB.x) ? -10000.f : s[2] * INV_NORM;
                s[3] = (gc + 1 > gr1 || mB.y) ? -10000.f : s[3] * INV_NORM;
                rm0 = fmaxf(rm0, fmaxf(s[0], s[1]));
                rm1 = fmaxf(rm1, fmaxf(s[2], s[3]));
            }
            rm0 = fmaxf(rm0, __shfl_xor_sync(0xffffffffu, rm0, 1));
            rm0 = fmaxf(rm0, __shfl_xor_sync(0xffffffffu, rm0, 2));
            rm1 = fmaxf(rm1, __shfl_xor_sync(0xffffffffu, rm1, 1));
            rm1 = fmaxf(rm1, __shfl_xor_sync(0xffffffffu, rm1, 2));
            if ((lane & 3) == 0) {
                warpmax[wn * 128 + lr]     = rm0;
                warpmax[wn * 128 + lr + 8] = rm1;
            }
        }
        __syncthreads();   // B: done reading K, warpmax visible

        // prefetch K(jt+1) into the now-free K buffer
        if (jt + 1 < ntiles) attn_load_K(sb, QKh, QKl, j0 + 64, kcol, bz, tid);
        asm volatile("cp.async.commit_group;\n" ::: "memory");

        if (tid < 128) {
            const float mold = m_sm[tid];
            const float mnew = fmaxf(mold, fmaxf(warpmax[tid], warpmax[128 + tid]));
            m_sm[tid]  = mnew;
            cf_sm[tid] = __expf(mold - mnew);
        }
        __syncthreads();   // C

        // ---- exp + store P (hi/lo) + row sums ----
#pragma unroll
        for (int mi = 0; mi < 2; ++mi) {
            const int lr = wm * 32 + mi * 16 + r0;
            const float m0v = m_sm[lr], m1v = m_sm[lr + 8];
            float rs0 = 0.f, rs1 = 0.f;
#pragma unroll
            for (int ni = 0; ni < 4; ++ni) {
                float* s = sacc[mi][ni];
                const float p0 = __expf(s[0] - m0v);
                const float p1 = __expf(s[1] - m0v);
                const float p2 = __expf(s[2] - m1v);
                const float p3 = __expf(s[3] - m1v);
                rs0 += p0 + p1;
                rs1 += p2 + p3;
                const int cbyte = (wn * 32 + ni * 8 + c0) * 2;
                const __nv_bfloat16 h0 = __float2bfloat16(p0);
                const __nv_bfloat16 h1 = __float2bfloat16(p1);
                const __nv_bfloat16 h2 = __float2bfloat16(p2);
                const __nv_bfloat16 h3 = __float2bfloat16(p3);
                *reinterpret_cast<uint32_t*>(smem + AT_PH + SWZ(lr * 128 + cbyte)) =
                    pack_hi(p0, p1);
                *reinterpret_cast<uint32_t*>(smem + AT_PH + SWZ((lr + 8) * 128 + cbyte)) =
                    pack_hi(p2, p3);
                *reinterpret_cast<uint32_t*>(smem + AT_PL + SWZ(lr * 128 + cbyte)) =
                    pack_lo(p0, p1, h0, h1);
                *reinterpret_cast<uint32_t*>(smem + AT_PL + SWZ((lr + 8) * 128 + cbyte)) =
                    pack_lo(p2, p3, h2, h3);
            }
            rs0 += __shfl_xor_sync(0xffffffffu, rs0, 1);
            rs0 += __shfl_xor_sync(0xffffffffu, rs0, 2);
            rs1 += __shfl_xor_sync(0xffffffffu, rs1, 1);
            rs1 += __shfl_xor_sync(0xffffffffu, rs1, 2);
            if ((lane & 3) == 0) {
                warpsum[wn * 128 + lr]     = rs0;
                warpsum[wn * 128 + lr + 8] = rs1;
            }
        }
        __syncthreads();   // D: P + warpsum visible
        if (tid < 128)
            l_sm[tid] = l_sm[tid] * cf_sm[tid] + warpsum[tid] + warpsum[128 + tid];

        asm volatile("cp.async.wait_group 1;\n" ::: "memory");  // V(jt) ready
        __syncthreads();   // F

        // ---- O-phase: O = O*cf + P @ Vt (128x128x64, split-bf16) ----
#pragma unroll
        for (int mi = 0; mi < 2; ++mi) {
            const int lr = wm * 32 + mi * 16 + r0;
            const float cfa = cf_sm[lr], cfb = cf_sm[lr + 8];
#pragma unroll
            for (int ni = 0; ni < 8; ++ni) {
                oacc[mi][ni][0] *= cfa; oacc[mi][ni][1] *= cfa;
                oacc[mi][ni][2] *= cfb; oacc[mi][ni][3] *= cfb;
            }
        }
#pragma unroll
        for (int kk = 0; kk < 4; ++kk) {
            const int kby = kk * 32;
            uint32_t ph[2][4], pl[2][4], vh[8][2], vl[8][2];
#pragma unroll
            for (int mi = 0; mi < 2; ++mi) {
                const int row = wm * 32 + mi * 16 + a_r;
                const uint32_t off = SWZ(row * 128 + kby + a_kb * 16);
                ldm_x4(sb + AT_PH + off, ph[mi][0], ph[mi][1], ph[mi][2], ph[mi][3]);
                ldm_x4(sb + AT_PL + off, pl[mi][0], pl[mi][1], pl[mi][2], pl[mi][3]);
            }
#pragma unroll
            for (int p = 0; p < 4; ++p) {
                const int row = wn * 64 + p * 16 + b_r;
                const uint32_t off = SWZ(row * 128 + kby + b_kb * 16);
                ldm_x4(sb + AT_VH + off,
                       vh[2 * p][0], vh[2 * p][1], vh[2 * p + 1][0], vh[2 * p + 1][1]);
                ldm_x4(sb + AT_VL + off,
                       vl[2 * p][0], vl[2 * p][1], vl[2 * p + 1][0], vl[2 * p + 1][1]);
            }
#pragma unroll
            for (int mi = 0; mi < 2; ++mi)
#pragma unroll
                for (int ni = 0; ni < 8; ++ni) {
                    mma16816(oacc[mi][ni], ph[mi], vh[ni]);
                    mma16816(oacc[mi][ni], ph[mi], vl[ni]);
                    mma16816(oacc[mi][ni], pl[mi], vh[ni]);
                }
        }
        __syncthreads();   // E: done reading V and P

        // prefetch V(jt+1) into the now-free V buffer
        if (jt + 1 < ntiles) attn_load_V(sb, Vth, Vtl, j0 + 64, bh, tid);
        asm volatile("cp.async.commit_group;\n" ::: "memory");
    }

    // ---- epilogue: normalize, split to bf16 hi/lo, write Ch/Cl ----
#pragma unroll
    for (int mi = 0; mi < 2; ++mi) {
        const int lr = wm * 32 + mi * 16 + r0;
        const float il0 = 1.0f / l_sm[lr];
        const float il1 = 1.0f / l_sm[lr + 8];
        const size_t grow0 = (size_t)(q0 + lr) * 2 + bz;
        const size_t grow1 = grow0 + 16;
#pragma unroll
        for (int ni = 0; ni < 8; ++ni) {
            const int col = head * DHEAD + wn * 64 + ni * 8 + c0;
            const float o0 = oacc[mi][ni][0] * il0, o1 = oacc[mi][ni][1] * il0;
            const float o2 = oacc[mi][ni][2] * il1, o3 = oacc[mi][ni][3] * il1;
            const __nv_bfloat16 h0 = __float2bfloat16(o0), h1 = __float2bfloat16(o1);
            const __nv_bfloat16 h2 = __float2bfloat16(o2), h3 = __float2bfloat16(o3);
            *reinterpret_cast<uint32_t*>(&Ch[grow0 * HID + col]) = pack_hi(o0, o1);
            *reinterpret_cast<uint32_t*>(&Ch[grow1 * HID + col]) = pack_hi(o2, o3);
            *reinterpret_cast<uint32_t*>(&Cl[grow0 * HID + col]) = pack_lo(o0, o1, h0, h1);
            *reinterpret_cast<uint32_t*>(&Cl[grow1 * HID + col]) = pack_lo(o2, o3, h2, h3);
        }
    }
}

// Tail: copy proj_bias after the main output if the harness expects it
__global__ void tail_bias_kernel(const float* __restrict__ bias,
                                 float* __restrict__ out, int n)
{
    const int i = blockIdx.x * blockDim.x + threadIdx.x;
    if (i < n) out[(size_t)NROWS * HID + i] = bias[i];
}

// ---------------------------------------------------------------------------
extern "C" void kernel_launch(void* const* d_in, const int* in_sizes, int n_in,
                              void* d_out, int out_size)
{
    const float*         hidden  = (const float*)d_in[0];
    const unsigned char* amask   = (const unsigned char*)d_in[1];
    const float*         qkv_w   = (const float*)d_in[2];
    const float*         qkv_b   = (const float*)d_in[3];
    const float*         proj_w  = (const float*)d_in[4];
    const float*         proj_b  = (const float*)d_in[5];
    float*               out     = (float*)d_out;

    __nv_bfloat16 *Ah, *Al, *Wqh, *Wql, *Wph, *Wpl, *Ch, *Cl, *QKh, *QKl, *Vth, *Vtl;
    cudaGetSymbolAddress((void**)&Ah,   g_Ah);
    cudaGetSymbolAddress((void**)&Al,   g_Al);
    cudaGetSymbolAddress((void**)&Wqh,  g_Wqh);
    cudaGetSymbolAddress((void**)&Wql,  g_Wql);
    cudaGetSymbolAddress((void**)&Wph,  g_Wph);
    cudaGetSymbolAddress((void**)&Wpl,  g_Wpl);
    cudaGetSymbolAddress((void**)&Ch,   g_Ch);
    cudaGetSymbolAddress((void**)&Cl,   g_Cl);
    cudaGetSymbolAddress((void**)&QKh,  g_qkvh);
    cudaGetSymbolAddress((void**)&QKl,  g_qkvl);
    cudaGetSymbolAddress((void**)&Vth,  g_Vth);
    cudaGetSymbolAddress((void**)&Vtl,  g_Vtl);

    cudaFuncSetAttribute(gemm_mma,
                         cudaFuncAttributeMaxDynamicSharedMemorySize, GSM_BYTES);
    cudaFuncSetAttribute(attn_mma,
                         cudaFuncAttributeMaxDynamicSharedMemorySize, ATT_SMEM);

    // 0) input conversions
    {
        const int n4 = (NROWS * HID) / 4;
        split_kernel<<<(n4 + 255) / 256, 256>>>(hidden, Ah, Al, n4);
        dim3 tb(32, 8);
        tsplit_kernel<<<dim3(H3 / 32, HID / 32), tb>>>(qkv_w, Wqh, Wql, HID, H3);
        tsplit_kernel<<<dim3(HID / 32, HID / 32), tb>>>(proj_w, Wph, Wpl, HID, HID);
    }
    // 1) QKV GEMM (mma.sync, 2 CTAs/SM), split epilogue -> qkvh/qkvl
    {
        dim3 grid(H3 / 64, NROWS / 128);
        gemm_mma<<<grid, 256, GSM_BYTES>>>(Ah, Al, Wqh, Wql, qkv_b, nullptr,
                                           QKh, QKl, NROWS, H3, HID);
    }
    // 2) V transpose (bf16 pass-through)
    {
        dim3 tb(32, 8);
        vtrans_kernel<<<dim3(S_LEN / 32, DHEAD / 32, BATCH * NHEADS), tb>>>(
            QKh, QKl, Vth, Vtl);
    }
    // 3) Attention (tensor cores, pipelined) -> Ch/Cl
    {
        dim3 grid(S_LEN / 128, NHEADS, BATCH);
        attn_mma<<<grid, 256, ATT_SMEM>>>(QKh, QKl, Vth, Vtl, amask, Ch, Cl);
    }
    // 4) Output projection (mma.sync, 2 CTAs/SM) -> fp32 out
    {
        dim3 grid(HID / 64, NROWS / 128);
        gemm_mma<<<grid, 256, GSM_BYTES>>>(Ch, Cl, Wph, Wpl, nullptr, out,
                                           nullptr, nullptr, NROWS, HID, HID);
    }
    // 5) Optional bias tail
    const long long main_elems = (long long)NROWS * HID;
    const long long extra = (long long)out_size - main_elems;
    if (extra > 0) {
        const int n = (int)extra;
        tail_bias_kernel<<<(n + 255) / 256, 256>>>(proj_b, out, n);
    }
}